// round 5
// baseline (speedup 1.0000x reference)
#include <cuda_runtime.h>
#include <stdint.h>
#include <math.h>

#define HH 512
#define WW 512
#define HWV (HH*WW)
#define NB 16
#define NB0 8
#define MM 2048
#define SCAP 32768

// ---------------- device scratch ----------------
__device__ float g_G[25];
__device__ float g_WC[51];
__device__ float g_WCP[52];          // prefix sums of WC
__device__ float g_t1a[NB*HWV];      // s-chain hconv of E (border-zeroed); later sm2
__device__ float g_t1b[NB*HWV];      // hd hconv
__device__ float g_t1c[NB*HWV];      // coverage hconv of E
__device__ float g_ps[NB*128];       // per-block sum of exp(score)
__device__ float g_mpart[NB*128*4];  // matchability partials: z, sd, sdv, sdlsd
__device__ int   g_svcnt[NB];
__device__ float g_svval[NB*SCAP];
__device__ int   g_svidx[NB*SCAP];
__device__ int   g_kidx[NB*MM];
__device__ float g_ssl[NB*MM];
__device__ unsigned char g_slg[NB*MM];
__device__ float g_lse[NB];
__device__ float g_spart[NB*16];

// ---------------- reduction helpers ----------------
__device__ __forceinline__ float blkMax1024(float v, float* red) {
  int t = threadIdx.x;
  red[t] = v; __syncthreads();
  for (int s = 512; s > 0; s >>= 1) {
    if (t < s) red[t] = fmaxf(red[t], red[t + s]);
    __syncthreads();
  }
  float r = red[0]; __syncthreads();
  return r;
}
__device__ __forceinline__ float blkSum1024(float v, float* red) {
  int t = threadIdx.x;
  red[t] = v; __syncthreads();
  for (int s = 512; s > 0; s >>= 1) {
    if (t < s) red[t] += red[t + s];
    __syncthreads();
  }
  float r = red[0]; __syncthreads();
  return r;
}
__device__ __forceinline__ float blkSum256(float v, float* red, int t) {
  red[t] = v; __syncthreads();
  for (int s = 128; s > 0; s >>= 1) {
    if (t < s) red[t] += red[t + s];
    __syncthreads();
  }
  float r = red[0]; __syncthreads();
  return r;
}
__device__ __forceinline__ float blkSum128(float v, float* red, int t) {
  red[t] = v; __syncthreads();
  for (int s = 64; s > 0; s >>= 1) {
    if (t < s) red[t] += red[t + s];
    __syncthreads();
  }
  float r = red[0]; __syncthreads();
  return r;
}

// ---------------- init ----------------
__global__ void k_init() {
  if (threadIdx.x == 0) {
    float g[25]; float s = 0.f;
    for (int i = 0; i < 25; i++) {
      float x = -1.0f + (2.0f / 24.0f) * (float)i;
      g[i] = expf(-x * x / 0.5f);
      s += g[i];
    }
    for (int i = 0; i < 25; i++) g_G[i] = g[i] / s;
    float p = 0.f;
    for (int i = 0; i < 51; i++) {
      float x = -2.0f + (4.0f / 50.0f) * (float)i;
      float w = expf(-x * x);
      g_WC[i] = w;
      g_WCP[i] = p;
      p += w;
    }
    g_WCP[51] = p;
  }
  if (threadIdx.x < NB) g_svcnt[threadIdx.x] = 0;
}

// ---------------- fused horizontal pass: exp + 3 convs + partial sums ----------------
// E = exp(score).  t1a = conv25(E) with W-border-zero bug.  t1c = conv51(E).
// t1b = conv25(hd).  g_ps = per-block sums of E.
__global__ __launch_bounds__(256) void k_hall(const float* __restrict__ score,
                                              const float* __restrict__ hd) {
  __shared__ float sE[4][568];   // RA=28 halo each side
  __shared__ float sD[4][536];   // RA=12
  __shared__ float red[256];
  int b = blockIdx.y;
  int tx = threadIdx.x, ty = threadIdx.y;    // (64,4)
  int h = blockIdx.x * 4 + ty;
  int tid = ty * 64 + tx;
  const float* srow = score + (size_t)b * HWV + (size_t)h * WW;
  const float* drow = hd + (size_t)b * HWV + (size_t)h * WW;
  float esum = 0.f;
  for (int c = tx; c < 568; c += 64) {
    int w = c - 28;
    float e = 0.f;
    if (w >= 0 && w < WW) e = __expf(srow[w]);
    sE[ty][c] = e;
    esum += e;
  }
  for (int c = tx; c < 536; c += 64) {
    int w = c - 12;
    sD[ty][c] = (w >= 0 && w < WW) ? drow[w] : 0.f;
  }
  __syncthreads();
  int wbase = 8 * tx;
  size_t obase = (size_t)b * HWV + (size_t)h * WW + wbase;
  // ---- coverage conv: 51 taps, window offset D=3 ----
  {
    float tp[51];
#pragma unroll
    for (int t = 0; t < 51; t++) tp[t] = g_WC[t];
    float acc[8];
#pragma unroll
    for (int k = 0; k < 8; k++) acc[k] = 0.f;
    const float4* w4 = (const float4*)&sE[ty][wbase];
#pragma unroll
    for (int g = 0; g < 16; g++) {
      float4 X = w4[g];
      float xs[4] = {X.x, X.y, X.z, X.w};
#pragma unroll
      for (int c = 0; c < 4; c++) {
        int q = 4 * g + c;
#pragma unroll
        for (int k = 0; k < 8; k++) {
          int t = q - 3 - k;
          if (t >= 0 && t <= 50) acc[k] = fmaf(tp[t], xs[c], acc[k]);
        }
      }
    }
    float4* o = (float4*)(g_t1c + obase);
    o[0] = make_float4(acc[0], acc[1], acc[2], acc[3]);
    o[1] = make_float4(acc[4], acc[5], acc[6], acc[7]);
  }
  // ---- s conv: 25 taps, window offset D=16, border-zero bug ----
  {
    float tp[25];
#pragma unroll
    for (int t = 0; t < 25; t++) tp[t] = g_G[t];
    float acc[8];
#pragma unroll
    for (int k = 0; k < 8; k++) acc[k] = 0.f;
    const float4* w4 = (const float4*)&sE[ty][wbase];
#pragma unroll
    for (int g = 4; g < 12; g++) {
      float4 X = w4[g];
      float xs[4] = {X.x, X.y, X.z, X.w};
#pragma unroll
      for (int c = 0; c < 4; c++) {
        int q = 4 * g + c;
#pragma unroll
        for (int k = 0; k < 8; k++) {
          int t = q - 16 - k;
          if (t >= 0 && t <= 24) acc[k] = fmaf(tp[t], xs[c], acc[k]);
        }
      }
    }
#pragma unroll
    for (int k = 0; k < 8; k++) {
      int w = wbase + k;
      if (w < 12 || w >= WW - 12) acc[k] = 0.f;
    }
    float4* o = (float4*)(g_t1a + obase);
    o[0] = make_float4(acc[0], acc[1], acc[2], acc[3]);
    o[1] = make_float4(acc[4], acc[5], acc[6], acc[7]);
  }
  // ---- hd conv: 25 taps, window offset D=0 ----
  {
    float tp[25];
#pragma unroll
    for (int t = 0; t < 25; t++) tp[t] = g_G[t];
    float acc[8];
#pragma unroll
    for (int k = 0; k < 8; k++) acc[k] = 0.f;
    const float4* w4 = (const float4*)&sD[ty][wbase];
#pragma unroll
    for (int g = 0; g < 8; g++) {
      float4 X = w4[g];
      float xs[4] = {X.x, X.y, X.z, X.w};
#pragma unroll
      for (int c = 0; c < 4; c++) {
        int q = 4 * g + c;
#pragma unroll
        for (int k = 0; k < 8; k++) {
          int t = q - k;
          if (t >= 0 && t <= 24) acc[k] = fmaf(tp[t], xs[c], acc[k]);
        }
      }
    }
    float4* o = (float4*)(g_t1b + obase);
    o[0] = make_float4(acc[0], acc[1], acc[2], acc[3]);
    o[1] = make_float4(acc[4], acc[5], acc[6], acc[7]);
  }
  esum = blkSum256(esum, red, tid);
  if (tid == 0) g_ps[b * 128 + blockIdx.x] = esum;
}

// ---------------- fused vertical convs (s + sd) + matchability partials ----------------
__global__ __launch_bounds__(256) void k_vmatch() {
  __shared__ float red[256];
  int b = blockIdx.z;
  int w = blockIdx.x * 32 + threadIdx.x;
  int hb = blockIdx.y * 64 + threadIdx.y * 8;
  int tid = threadIdx.y * 32 + threadIdx.x;
  float pv = (tid < 128) ? g_ps[b * 128 + tid] : 0.f;
  float Z = blkSum256(pv, red, tid);
  float invz = 1.0f / Z;
  float tp[25];
#pragma unroll
  for (int t = 0; t < 25; t++) tp[t] = g_G[t];
  const float* ps = g_t1a + (size_t)b * HWV;
  const float* pd = g_t1b + (size_t)b * HWV;
  float as[8], ad[8];
#pragma unroll
  for (int k = 0; k < 8; k++) { as[k] = 0.f; ad[k] = 0.f; }
#pragma unroll
  for (int r = 0; r < 32; r++) {
    int hh = hb - 12 + r;
    float xs = 0.f, xd = 0.f;
    if (hh >= 0 && hh < HH) {
      size_t idx = (size_t)hh * WW + w;
      xs = ps[idx]; xd = pd[idx];
    }
#pragma unroll
    for (int k = 0; k < 8; k++) {
      int t = r - k;
      if (t >= 0 && t <= 24) {
        as[k] = fmaf(tp[t], xs, as[k]);
        ad[k] = fmaf(tp[t], xd, ad[k]);
      }
    }
  }
  float zsum = 0.f, sdsum = 0.f, sdv = 0.f, sdlsd = 0.f;
#pragma unroll
  for (int k = 0; k < 8; k++) {
    float s = fmaf(invz, as[k], 1e-8f);
    float v = __logf(s);
    zsum += s;
    float sd = ad[k];
    sdsum += sd;
    if (sd > 0.f) {
      sdv = fmaf(sd, v, sdv);
      sdlsd = fmaf(sd, __logf(sd), sdlsd);
    }
  }
  zsum = blkSum256(zsum, red, tid);
  sdsum = blkSum256(sdsum, red, tid);
  sdv = blkSum256(sdv, red, tid);
  sdlsd = blkSum256(sdlsd, red, tid);
  if (tid == 0) {
    int bi = blockIdx.y * 16 + blockIdx.x;
    float* p = g_mpart + ((size_t)b * 128 + bi) * 4;
    p[0] = zsum; p[1] = sdsum; p[2] = sdv; p[3] = sdlsd;
  }
}

// ---------------- vertical coverage conv + border correction + reweight ----------------
__global__ __launch_bounds__(256) void k_vcov(const float* __restrict__ score) {
  __shared__ float red[256];
  int b = blockIdx.z;
  int w = blockIdx.x * 32 + threadIdx.x;
  int hb = blockIdx.y * 64 + threadIdx.y * 8;
  int tid = threadIdx.y * 32 + threadIdx.x;
  float pv = (tid < 128) ? g_ps[b * 128 + tid] : 0.f;
  float Z = blkSum256(pv, red, tid);
  float invz = 1.0f / Z;
  float tp[51];
#pragma unroll
  for (int t = 0; t < 51; t++) tp[t] = g_WC[t];
  const float* pin = g_t1c + (size_t)b * HWV;
  float acc[8];
#pragma unroll
  for (int k = 0; k < 8; k++) acc[k] = 0.f;
#pragma unroll
  for (int r = 0; r < 58; r++) {
    int hh = hb - 25 + r;
    float x = 0.f;
    if (hh >= 0 && hh < HH) x = pin[(size_t)hh * WW + w];
#pragma unroll
    for (int k = 0; k < 8; k++) {
      int t = r - k;
      if (t >= 0 && t <= 50) acc[k] = fmaf(tp[t], x, acc[k]);
    }
  }
  int jlo = (25 - w > 0) ? (25 - w) : 0;
  int jhi = (536 - w < 50) ? (536 - w) : 50;
  float Tw = g_WCP[jhi + 1] - g_WCP[jlo];
  const float* sc = score + (size_t)b * HWV;
  float* po = g_t1a + (size_t)b * HWV;   // reuse t1a as sm2 (vmatch already consumed it)
#pragma unroll
  for (int k = 0; k < 8; k++) {
    int hg = hb + k;
    int ilo = (25 - hg > 0) ? (25 - hg) : 0;
    int ihi = (536 - hg < 50) ? (536 - hg) : 50;
    float Tv = g_WCP[ihi + 1] - g_WCP[ilo];
    float ld = 1e4f * (invz * acc[k] + 1e-6f * Tw * Tv);
    size_t oi = (size_t)hg * WW + w;
    po[oi] = __expf(sc[oi]) * invz * rsqrtf(ld + 1e-8f);
  }
}

// ---------------- fused 5x5 NMS + survivor compaction ----------------
__global__ __launch_bounds__(256) void k_nms5(const float* __restrict__ sm2) {
  __shared__ float sh[36 * 36];
  __shared__ float rm[36 * 32];
  int b = blockIdx.z;
  int h0 = blockIdx.y * 32, w0 = blockIdx.x * 32;
  int t = threadIdx.y * 32 + threadIdx.x;
  const float* img = sm2 + (size_t)b * HWV;
  for (int i = t; i < 36 * 36; i += 256) {
    int r = i / 36, c = i - r * 36;
    int hh = h0 - 2 + r, ww = w0 - 2 + c;
    sh[i] = (hh >= 0 && hh < HH && ww >= 0 && ww < WW) ? img[(size_t)hh * WW + ww] : -INFINITY;
  }
  __syncthreads();
  for (int i = t; i < 36 * 32; i += 256) {
    int r = i >> 5, c = i & 31;
    const float* p = sh + r * 36 + c;
    rm[r * 32 + c] = fmaxf(fmaxf(fmaxf(p[0], p[1]), fmaxf(p[2], p[3])), p[4]);
  }
  __syncthreads();
#pragma unroll
  for (int s = 0; s < 4; s++) {
    int r = threadIdx.y + s * 8;
    int c = threadIdx.x;
    const float* p = rm + r * 32 + c;
    float m = fmaxf(fmaxf(fmaxf(p[0], p[32]), fmaxf(p[64], p[96])), p[128]);
    float val = sh[(r + 2) * 36 + (c + 2)];
    if (val == m) {
      int pp = atomicAdd(&g_svcnt[b], 1);
      if (pp < SCAP) {
        g_svval[(size_t)b * SCAP + pp] = val;
        g_svidx[(size_t)b * SCAP + pp] = (h0 + r) * WW + (w0 + c);
      }
    }
  }
}

// ---------------- top-2048 radix select + gather + masked LSE ----------------
__global__ __launch_bounds__(1024) void k_topk(const float* __restrict__ scoremap,
                                               const float* __restrict__ vA,
                                               const float* __restrict__ vB) {
  int x = blockIdx.x;
  int n = g_svcnt[x]; if (n > SCAP) n = SCAP;
  const float* vals = g_svval + (size_t)x * SCAP;
  const int* idxs = g_svidx + (size_t)x * SCAP;
  int* out = g_kidx + (size_t)x * MM;
  __shared__ int hist[256];
  __shared__ float red[1024];
  __shared__ int sh_k, sh_dig, sh_ngt, sh_neq;
  int t = threadIdx.x;
  unsigned int prefix = 0;
  int k = MM;
  for (int lvl = 0; lvl < 4; lvl++) {
    int shift = 24 - 8 * lvl;
    if (t < 256) hist[t] = 0;
    __syncthreads();
    for (int i = t; i < n; i += 1024) {
      unsigned int u = __float_as_uint(vals[i]);
      bool ok = (lvl == 0) || ((u >> (shift + 8)) == (prefix >> (shift + 8)));
      if (ok) atomicAdd(&hist[(u >> shift) & 255], 1);
    }
    __syncthreads();
    if (t == 0) {
      int acc = 0, d;
      for (d = 255; d >= 0; d--) {
        if (acc + hist[d] >= k) break;
        acc += hist[d];
      }
      if (d < 0) d = 0;
      sh_k = k - acc; sh_dig = d;
    }
    __syncthreads();
    k = sh_k;
    prefix |= ((unsigned int)sh_dig) << shift;
    __syncthreads();
  }
  unsigned int T = prefix;
  if (t == 0) { sh_ngt = 0; sh_neq = 0; }
  __syncthreads();
  for (int i = t; i < n; i += 1024) {
    unsigned int u = __float_as_uint(vals[i]);
    if (u > T) { int p = atomicAdd(&sh_ngt, 1); if (p < MM) out[p] = idxs[i]; }
  }
  __syncthreads();
  int base = sh_ngt;
  for (int i = t; i < n; i += 1024) {
    unsigned int u = __float_as_uint(vals[i]);
    if (u == T) { int p = atomicAdd(&sh_neq, 1); if (base + p < MM) out[base + p] = idxs[i]; }
  }
  __syncthreads();
  int dir = (x >= NB0) ? 1 : 0;
  int b = dir ? x - NB0 : x;
  const float* valid = (dir ? vB : vA) + (size_t)b * HWV;
  const float* logit = scoremap + (size_t)x * HWV;
  float mv = -INFINITY;
  for (int i = t; i < MM; i += 1024) {
    int id = out[i];
    float sl = logit[id];
    unsigned char lg = (valid[id] > 0.f) ? 1 : 0;
    g_ssl[(size_t)x * MM + i] = sl;
    g_slg[(size_t)x * MM + i] = lg;
    mv = fmaxf(mv, lg ? sl : -1e9f);
  }
  mv = blkMax1024(mv, red);
  float z = 0.f;
  for (int i = t; i < MM; i += 1024) {
    float ml = g_slg[(size_t)x * MM + i] ? g_ssl[(size_t)x * MM + i] : -1e9f;
    z += expf(ml - mv);
  }
  z = blkSum1024(z, red);
  if (t == 0) g_lse[x] = mv + logf(z);
}

// ---------------- distance + reward + weighted loss partials ----------------
__global__ __launch_bounds__(128) void k_dist(const float* __restrict__ wA,
                                              const float* __restrict__ wB) {
  __shared__ float4 sp[MM];
  __shared__ float red[128];
  int x = blockIdx.x, seg = blockIdx.y;
  int dir = (x >= NB0) ? 1 : 0;
  int b = dir ? x - NB0 : x;
  int oppx = dir ? b : (NB0 + b);
  const int* opp = g_kidx + (size_t)oppx * MM;
  const int* own = g_kidx + (size_t)x * MM;
  const float4* warp = (const float4*)((dir ? wB : wA) + (size_t)b * HWV * 4);
  int t = threadIdx.x;
  for (int i = t; i < MM; i += 128) {
    int id = opp[i]; int hh = id >> 9, ww = id & 511;
    float px = ((float)ww + 0.5f) * (2.0f / (float)WW) - 1.0f;
    float py = ((float)hh + 0.5f) * (2.0f / (float)HH) - 1.0f;
    sp[i] = make_float4(2.0f * px, 2.0f * py, fmaf(px, px, py * py), 0.f);
  }
  __syncthreads();
  int i = seg * 128 + t;
  int id = own[i];
  float4 wp = warp[id];
  float txc = wp.z, tyc = wp.w;
  float m0 = -3.4e38f, m1 = -3.4e38f, m2 = -3.4e38f, m3 = -3.4e38f;
#pragma unroll 2
  for (int j = 0; j < MM; j += 4) {
    float4 p0 = sp[j], p1 = sp[j + 1], p2 = sp[j + 2], p3 = sp[j + 3];
    m0 = fmaxf(m0, fmaf(p0.x, txc, fmaf(p0.y, tyc, -p0.z)));
    m1 = fmaxf(m1, fmaf(p1.x, txc, fmaf(p1.y, tyc, -p1.z)));
    m2 = fmaxf(m2, fmaf(p2.x, txc, fmaf(p2.y, tyc, -p2.z)));
    m3 = fmaxf(m3, fmaf(p3.x, txc, fmaf(p3.y, tyc, -p3.z)));
  }
  float m = fmaxf(fmaxf(m0, m1), fmaxf(m2, m3));
  float dmin = fmaxf(fmaf(txc, txc, tyc * tyc) - m, 0.f);
  float r = expf(-100.0f * sqrtf(dmin + 1e-12f));
  float lse = g_lse[x];
  float contrib = g_slg[(size_t)x * MM + i] ? r * (g_ssl[(size_t)x * MM + i] - lse) : 0.f;
  contrib = blkSum128(contrib, red, t);
  if (t == 0) g_spart[x * 16 + seg] = contrib;
}

// ---------------- final combine ----------------
__global__ __launch_bounds__(256) void k_final(float* __restrict__ out) {
  __shared__ float sZ[128], sS[128], sV[128], sD[128];
  __shared__ float sm[16];
  __shared__ float ssp[256];
  int t = threadIdx.x;
  if (t < 128) {
    int img = t >> 3, seg = t & 7;
    float z = 0.f, s = 0.f, v = 0.f, d = 0.f;
    for (int j = 0; j < 16; j++) {
      const float* p = g_mpart + ((size_t)img * 128 + seg * 16 + j) * 4;
      z += p[0]; s += p[1]; v += p[2]; d += p[3];
    }
    sZ[t] = z; sS[t] = s; sV[t] = v; sD[t] = d;
  }
  ssp[t] = g_spart[t];
  __syncthreads();
  if (t < 16) {
    float z = 0.f, s = 0.f, v = 0.f, d = 0.f;
    for (int seg = 0; seg < 8; seg++) {
      z += sZ[t * 8 + seg]; s += sS[t * 8 + seg];
      v += sV[t * 8 + seg]; d += sD[t * 8 + seg];
    }
    float inv = 1.0f / s;
    sm[t] = inv * (d - v) - logf(s) + logf(z);
  }
  __syncthreads();
  if (t == 0) {
    float sp = 0.f;
    for (int i = 0; i < 256; i++) sp += ssp[i];
    float m = 0.f;
    for (int i = 0; i < 16; i++) m += sm[i];
    out[0] = -sp + m * (1.0f / 16.0f);
  }
}

// ---------------- host launcher ----------------
extern "C" void kernel_launch(void* const* d_in, const int* in_sizes, int n_in,
                              void* d_out, int out_size) {
  (void)in_sizes; (void)n_in; (void)out_size;
  const float* scoremap = (const float*)d_in[0];
  const float* wA = (const float*)d_in[1];
  const float* wB = (const float*)d_in[2];
  const float* vA = (const float*)d_in[3];
  const float* vB = (const float*)d_in[4];
  const float* hd = (const float*)d_in[5];
  float* out = (float*)d_out;

  void* p_a = 0;
  cudaGetSymbolAddress(&p_a, g_t1a);

  dim3 hg(HH / 4, NB);
  dim3 hb(64, 4);
  dim3 vg(WW / 32, HH / 64, NB);
  dim3 vb(32, 8);
  dim3 ng(WW / 32, HH / 32, NB);
  dim3 nb(32, 8);
  dim3 dg(NB, 16);

  k_init<<<1, 32>>>();
  k_hall<<<hg, hb>>>(scoremap, hd);
  k_vmatch<<<vg, vb>>>();
  k_vcov<<<vg, vb>>>(scoremap);
  k_nms5<<<ng, nb>>>((const float*)p_a);
  k_topk<<<NB, 1024>>>(scoremap, vA, vB);
  k_dist<<<dg, 128>>>(wA, wB);
  k_final<<<1, 256>>>(out);
}

// round 6
// speedup vs baseline: 1.0947x; 1.0947x over previous
#include <cuda_runtime.h>
#include <stdint.h>
#include <math.h>

#define HH 512
#define WW 512
#define HWV (HH*WW)
#define NB 16
#define NB0 8
#define MM 2048
#define SCAP 32768

// ---------------- compile-time taps ----------------
__host__ __device__ constexpr double cexp(double x) {
  double y = x < 0 ? -x : x;
  int n = (int)y;
  double f = y - n;
  double term = 1.0, sum = 1.0;
  for (int i = 1; i < 28; i++) { term = term * f / (double)i; sum += term; }
  double en = 1.0;
  for (int i = 0; i < n; i++) en *= 2.71828182845904523536028747135;
  double r = en * sum;
  return x < 0 ? 1.0 / r : r;
}
__host__ __device__ constexpr float gtap(int i) {
  double s = 0.0, gi = 0.0;
  for (int j = 0; j < 25; j++) {
    double xx = -1.0 + 2.0 * (double)j / 24.0;
    double g = cexp(-xx * xx / 0.5);
    if (j == i) gi = g;
    s += g;
  }
  return (float)(gi / s);
}
__host__ __device__ constexpr float wctap(int i) {
  double xx = -2.0 + 4.0 * (double)i / 50.0;
  return (float)cexp(-xx * xx);
}
template<int TSEL, int T> __device__ __forceinline__ float tapv() {
  constexpr float v = (TSEL == 0) ? gtap(T) : wctap(T);
  return v;
}

// scatter one input sample into KMAX accumulators; tap index t = Q - D - K (immediate)
template<int K, int KMAX, int Q, int D, int TMAX, int TSEL>
__device__ __forceinline__ void scat(float x, float* acc) {
  if constexpr (K < KMAX) {
    constexpr int t = Q - D - K;
    if constexpr (t >= 0 && t <= TMAX) {
      acc[K] = fmaf(tapv<TSEL, (t >= 0 && t <= TMAX) ? t : 0>(), x, acc[K]);
    }
    scat<K + 1, KMAX, Q, D, TMAX, TSEL>(x, acc);
  }
}
// horizontal: iterate float4 groups of the per-thread shared window
template<int G4, int GMAX, int KMAX, int D, int TMAX, int TSEL>
__device__ __forceinline__ void conv4(const float4* w4, float* acc) {
  if constexpr (G4 < GMAX) {
    float4 X = w4[G4];
    scat<0, KMAX, 4 * G4 + 0, D, TMAX, TSEL>(X.x, acc);
    scat<0, KMAX, 4 * G4 + 1, D, TMAX, TSEL>(X.y, acc);
    scat<0, KMAX, 4 * G4 + 2, D, TMAX, TSEL>(X.z, acc);
    scat<0, KMAX, 4 * G4 + 3, D, TMAX, TSEL>(X.w, acc);
    conv4<G4 + 1, GMAX, KMAX, D, TMAX, TSEL>(w4, acc);
  }
}
// vertical: strided global loads, optional bounds check
template<int R, int RMAX, int KMAX, int TMAX, int TSEL, bool CHK>
__device__ __forceinline__ void vloop(const float* p, int hlo, float* acc) {
  if constexpr (R < RMAX) {
    float x = 0.f;
    if (!CHK || ((unsigned)(hlo + R) < (unsigned)HH)) x = p[(size_t)R * WW];
    scat<0, KMAX, R, 0, TMAX, TSEL>(x, acc);
    vloop<R + 1, RMAX, KMAX, TMAX, TSEL, CHK>(p, hlo, acc);
  }
}
template<int R, int RMAX, bool CHK>
__device__ __forceinline__ void vmloop(const float* ps, const float* pd, int hlo,
                                       float* as, float* ad) {
  if constexpr (R < RMAX) {
    float xs = 0.f, xd = 0.f;
    if (!CHK || ((unsigned)(hlo + R) < (unsigned)HH)) {
      xs = ps[(size_t)R * WW];
      xd = pd[(size_t)R * WW];
    }
    scat<0, 8, R, 0, 24, 0>(xs, as);
    scat<0, 8, R, 0, 24, 0>(xd, ad);
    vmloop<R + 1, RMAX, CHK>(ps, pd, hlo, as, ad);
  }
}

// ---------------- device scratch ----------------
__device__ float g_WCP[52];          // runtime prefix sums of WC (runtime-indexed)
__device__ float g_t1a[NB*HWV];      // s-chain hconv (border-zeroed); later sm2
__device__ float g_t1b[NB*HWV];      // hd hconv
__device__ float g_t1c[NB*HWV];      // coverage hconv of E
__device__ float g_ps[NB*128];       // per-block sum of exp(score)
__device__ float g_mpart[NB*128*4];  // matchability partials: z, sd, sdv, sdlsd
__device__ int   g_svcnt[NB];
__device__ float g_svval[NB*SCAP];
__device__ int   g_svidx[NB*SCAP];
__device__ int   g_kidx[NB*MM];
__device__ float g_ssl[NB*MM];
__device__ unsigned char g_slg[NB*MM];
__device__ float g_lse[NB];
__device__ float g_spart[NB*16];

// ---------------- reduction helpers ----------------
__device__ __forceinline__ float blkMax1024(float v, float* red) {
  int t = threadIdx.x;
  red[t] = v; __syncthreads();
  for (int s = 512; s > 0; s >>= 1) {
    if (t < s) red[t] = fmaxf(red[t], red[t + s]);
    __syncthreads();
  }
  float r = red[0]; __syncthreads();
  return r;
}
__device__ __forceinline__ float blkSum1024(float v, float* red) {
  int t = threadIdx.x;
  red[t] = v; __syncthreads();
  for (int s = 512; s > 0; s >>= 1) {
    if (t < s) red[t] += red[t + s];
    __syncthreads();
  }
  float r = red[0]; __syncthreads();
  return r;
}
__device__ __forceinline__ float blkSum256(float v, float* red, int t) {
  red[t] = v; __syncthreads();
  for (int s = 128; s > 0; s >>= 1) {
    if (t < s) red[t] += red[t + s];
    __syncthreads();
  }
  float r = red[0]; __syncthreads();
  return r;
}
__device__ __forceinline__ float blkSum128(float v, float* red, int t) {
  red[t] = v; __syncthreads();
  for (int s = 64; s > 0; s >>= 1) {
    if (t < s) red[t] += red[t + s];
    __syncthreads();
  }
  float r = red[0]; __syncthreads();
  return r;
}

// ---------------- init ----------------
__global__ void k_init() {
  if (threadIdx.x == 0) {
    float p = 0.f;
    for (int i = 0; i < 51; i++) {
      float x = -2.0f + (4.0f / 50.0f) * (float)i;
      g_WCP[i] = p;
      p += expf(-x * x);
    }
    g_WCP[51] = p;
  }
  if (threadIdx.x < NB) g_svcnt[threadIdx.x] = 0;
}

// ---------------- fused horizontal pass: exp + 3 convs + partial sums ----------------
__global__ __launch_bounds__(256) void k_hall(const float* __restrict__ score,
                                              const float* __restrict__ hd) {
  __shared__ float sE[4][568];   // halo 28 each side
  __shared__ float sD[4][536];   // halo 12
  __shared__ float red[256];
  int b = blockIdx.y;
  int tx = threadIdx.x, ty = threadIdx.y;    // (64,4)
  int h = blockIdx.x * 4 + ty;
  int tid = ty * 64 + tx;
  const float* srow = score + (size_t)b * HWV + (size_t)h * WW;
  const float* drow = hd + (size_t)b * HWV + (size_t)h * WW;
  float esum = 0.f;
  for (int c = tx; c < 568; c += 64) {
    int w = c - 28;
    float e = 0.f;
    if (w >= 0 && w < WW) e = __expf(srow[w]);
    sE[ty][c] = e;
    esum += e;
  }
  for (int c = tx; c < 536; c += 64) {
    int w = c - 12;
    sD[ty][c] = (w >= 0 && w < WW) ? drow[w] : 0.f;
  }
  __syncthreads();
  int wbase = 8 * tx;
  size_t obase = (size_t)b * HWV + (size_t)h * WW + wbase;
  // coverage conv: 51 taps, D=3
  {
    float acc[8];
#pragma unroll
    for (int k = 0; k < 8; k++) acc[k] = 0.f;
    conv4<0, 16, 8, 3, 50, 1>((const float4*)&sE[ty][wbase], acc);
    float4* o = (float4*)(g_t1c + obase);
    o[0] = make_float4(acc[0], acc[1], acc[2], acc[3]);
    o[1] = make_float4(acc[4], acc[5], acc[6], acc[7]);
  }
  // s conv: 25 taps, D=16, W-border-zero bug
  {
    float acc[8];
#pragma unroll
    for (int k = 0; k < 8; k++) acc[k] = 0.f;
    conv4<4, 12, 8, 16, 24, 0>((const float4*)&sE[ty][wbase], acc);
#pragma unroll
    for (int k = 0; k < 8; k++) {
      int w = wbase + k;
      if (w < 12 || w >= WW - 12) acc[k] = 0.f;
    }
    float4* o = (float4*)(g_t1a + obase);
    o[0] = make_float4(acc[0], acc[1], acc[2], acc[3]);
    o[1] = make_float4(acc[4], acc[5], acc[6], acc[7]);
  }
  // hd conv: 25 taps, D=0
  {
    float acc[8];
#pragma unroll
    for (int k = 0; k < 8; k++) acc[k] = 0.f;
    conv4<0, 8, 8, 0, 24, 0>((const float4*)&sD[ty][wbase], acc);
    float4* o = (float4*)(g_t1b + obase);
    o[0] = make_float4(acc[0], acc[1], acc[2], acc[3]);
    o[1] = make_float4(acc[4], acc[5], acc[6], acc[7]);
  }
  esum = blkSum256(esum, red, tid);
  if (tid == 0) g_ps[b * 128 + blockIdx.x] = esum;
}

// ---------------- fused vertical convs (s + sd) + matchability partials ----------------
__global__ __launch_bounds__(256) void k_vmatch() {
  __shared__ float red[256];
  int b = blockIdx.z;
  int w = blockIdx.x * 32 + threadIdx.x;
  int hb = blockIdx.y * 64 + threadIdx.y * 8;
  int tid = threadIdx.y * 32 + threadIdx.x;
  float pv = (tid < 128) ? g_ps[b * 128 + tid] : 0.f;
  float Z = blkSum256(pv, red, tid);
  float invz = 1.0f / Z;
  const float* ps = g_t1a + (size_t)b * HWV;
  const float* pd = g_t1b + (size_t)b * HWV;
  float as[8], ad[8];
#pragma unroll
  for (int k = 0; k < 8; k++) { as[k] = 0.f; ad[k] = 0.f; }
  int hlo = hb - 12;
  const float* pps = ps + (size_t)hlo * WW + w;
  const float* ppd = pd + (size_t)hlo * WW + w;
  if (hlo >= 0 && hlo + 31 < HH) vmloop<0, 32, false>(pps, ppd, hlo, as, ad);
  else                           vmloop<0, 32, true>(pps, ppd, hlo, as, ad);
  float zsum = 0.f, sdsum = 0.f, sdv = 0.f, sdlsd = 0.f;
#pragma unroll
  for (int k = 0; k < 8; k++) {
    float s = fmaf(invz, as[k], 1e-8f);
    float v = __logf(s);
    zsum += s;
    float sd = ad[k];
    sdsum += sd;
    if (sd > 0.f) {
      sdv = fmaf(sd, v, sdv);
      sdlsd = fmaf(sd, __logf(sd), sdlsd);
    }
  }
  zsum = blkSum256(zsum, red, tid);
  sdsum = blkSum256(sdsum, red, tid);
  sdv = blkSum256(sdv, red, tid);
  sdlsd = blkSum256(sdlsd, red, tid);
  if (tid == 0) {
    int bi = blockIdx.y * 16 + blockIdx.x;
    float* p = g_mpart + ((size_t)b * 128 + bi) * 4;
    p[0] = zsum; p[1] = sdsum; p[2] = sdv; p[3] = sdlsd;
  }
}

// ---------------- vertical coverage conv + border correction + reweight ----------------
__global__ __launch_bounds__(256) void k_vcov(const float* __restrict__ score) {
  __shared__ float red[256];
  int b = blockIdx.z;
  int w = blockIdx.x * 32 + threadIdx.x;
  int hb = blockIdx.y * 128 + threadIdx.y * 16;
  int tid = threadIdx.y * 32 + threadIdx.x;
  float pv = (tid < 128) ? g_ps[b * 128 + tid] : 0.f;
  float Z = blkSum256(pv, red, tid);
  float invz = 1.0f / Z;
  const float* pin = g_t1c + (size_t)b * HWV;
  float acc[16];
#pragma unroll
  for (int k = 0; k < 16; k++) acc[k] = 0.f;
  int hlo = hb - 25;
  const float* p = pin + (size_t)hlo * WW + w;
  if (hlo >= 0 && hlo + 65 < HH) vloop<0, 66, 16, 50, 1, false>(p, hlo, acc);
  else                           vloop<0, 66, 16, 50, 1, true>(p, hlo, acc);
  int jlo = (25 - w > 0) ? (25 - w) : 0;
  int jhi = (536 - w < 50) ? (536 - w) : 50;
  float Tw = g_WCP[jhi + 1] - g_WCP[jlo];
  const float* sc = score + (size_t)b * HWV;
  float* po = g_t1a + (size_t)b * HWV;   // reuse t1a as sm2 (vmatch already consumed it)
#pragma unroll
  for (int k = 0; k < 16; k++) {
    int hg = hb + k;
    int ilo = (25 - hg > 0) ? (25 - hg) : 0;
    int ihi = (536 - hg < 50) ? (536 - hg) : 50;
    float Tv = g_WCP[ihi + 1] - g_WCP[ilo];
    float ld = 1e4f * (invz * acc[k] + 1e-6f * Tw * Tv);
    size_t oi = (size_t)hg * WW + w;
    po[oi] = __expf(sc[oi]) * invz * rsqrtf(ld + 1e-8f);
  }
}

// ---------------- fused 5x5 NMS + survivor compaction ----------------
__global__ __launch_bounds__(256) void k_nms5(const float* __restrict__ sm2) {
  __shared__ float sh[36 * 36];
  __shared__ float rm[36 * 32];
  int b = blockIdx.z;
  int h0 = blockIdx.y * 32, w0 = blockIdx.x * 32;
  int t = threadIdx.y * 32 + threadIdx.x;
  const float* img = sm2 + (size_t)b * HWV;
  for (int i = t; i < 36 * 36; i += 256) {
    int r = i / 36, c = i - r * 36;
    int hh = h0 - 2 + r, ww = w0 - 2 + c;
    sh[i] = (hh >= 0 && hh < HH && ww >= 0 && ww < WW) ? img[(size_t)hh * WW + ww] : -INFINITY;
  }
  __syncthreads();
  for (int i = t; i < 36 * 32; i += 256) {
    int r = i >> 5, c = i & 31;
    const float* p = sh + r * 36 + c;
    rm[r * 32 + c] = fmaxf(fmaxf(fmaxf(p[0], p[1]), fmaxf(p[2], p[3])), p[4]);
  }
  __syncthreads();
#pragma unroll
  for (int s = 0; s < 4; s++) {
    int r = threadIdx.y + s * 8;
    int c = threadIdx.x;
    const float* p = rm + r * 32 + c;
    float m = fmaxf(fmaxf(fmaxf(p[0], p[32]), fmaxf(p[64], p[96])), p[128]);
    float val = sh[(r + 2) * 36 + (c + 2)];
    if (val == m) {
      int pp = atomicAdd(&g_svcnt[b], 1);
      if (pp < SCAP) {
        g_svval[(size_t)b * SCAP + pp] = val;
        g_svidx[(size_t)b * SCAP + pp] = (h0 + r) * WW + (w0 + c);
      }
    }
  }
}

// ---------------- top-2048 radix select + gather + masked LSE ----------------
__global__ __launch_bounds__(1024) void k_topk(const float* __restrict__ scoremap,
                                               const float* __restrict__ vA,
                                               const float* __restrict__ vB) {
  int x = blockIdx.x;
  int n = g_svcnt[x]; if (n > SCAP) n = SCAP;
  const float* vals = g_svval + (size_t)x * SCAP;
  const int* idxs = g_svidx + (size_t)x * SCAP;
  int* out = g_kidx + (size_t)x * MM;
  __shared__ int hist[256];
  __shared__ float red[1024];
  __shared__ int sh_k, sh_dig, sh_ngt, sh_neq;
  int t = threadIdx.x;
  unsigned int prefix = 0;
  int k = MM;
  for (int lvl = 0; lvl < 4; lvl++) {
    int shift = 24 - 8 * lvl;
    if (t < 256) hist[t] = 0;
    __syncthreads();
    for (int i = t; i < n; i += 1024) {
      unsigned int u = __float_as_uint(vals[i]);
      bool ok = (lvl == 0) || ((u >> (shift + 8)) == (prefix >> (shift + 8)));
      if (ok) atomicAdd(&hist[(u >> shift) & 255], 1);
    }
    __syncthreads();
    if (t == 0) {
      int acc = 0, d;
      for (d = 255; d >= 0; d--) {
        if (acc + hist[d] >= k) break;
        acc += hist[d];
      }
      if (d < 0) d = 0;
      sh_k = k - acc; sh_dig = d;
    }
    __syncthreads();
    k = sh_k;
    prefix |= ((unsigned int)sh_dig) << shift;
    __syncthreads();
  }
  unsigned int T = prefix;
  if (t == 0) { sh_ngt = 0; sh_neq = 0; }
  __syncthreads();
  for (int i = t; i < n; i += 1024) {
    unsigned int u = __float_as_uint(vals[i]);
    if (u > T) { int p = atomicAdd(&sh_ngt, 1); if (p < MM) out[p] = idxs[i]; }
  }
  __syncthreads();
  int base = sh_ngt;
  for (int i = t; i < n; i += 1024) {
    unsigned int u = __float_as_uint(vals[i]);
    if (u == T) { int p = atomicAdd(&sh_neq, 1); if (base + p < MM) out[base + p] = idxs[i]; }
  }
  __syncthreads();
  int dir = (x >= NB0) ? 1 : 0;
  int b = dir ? x - NB0 : x;
  const float* valid = (dir ? vB : vA) + (size_t)b * HWV;
  const float* logit = scoremap + (size_t)x * HWV;
  float mv = -INFINITY;
  for (int i = t; i < MM; i += 1024) {
    int id = out[i];
    float sl = logit[id];
    unsigned char lg = (valid[id] > 0.f) ? 1 : 0;
    g_ssl[(size_t)x * MM + i] = sl;
    g_slg[(size_t)x * MM + i] = lg;
    mv = fmaxf(mv, lg ? sl : -1e9f);
  }
  mv = blkMax1024(mv, red);
  float z = 0.f;
  for (int i = t; i < MM; i += 1024) {
    float ml = g_slg[(size_t)x * MM + i] ? g_ssl[(size_t)x * MM + i] : -1e9f;
    z += expf(ml - mv);
  }
  z = blkSum1024(z, red);
  if (t == 0) g_lse[x] = mv + logf(z);
}

// ---------------- distance + reward + weighted loss partials ----------------
__global__ __launch_bounds__(128) void k_dist(const float* __restrict__ wA,
                                              const float* __restrict__ wB) {
  __shared__ float4 sp[MM];
  __shared__ float red[128];
  int x = blockIdx.x, seg = blockIdx.y;
  int dir = (x >= NB0) ? 1 : 0;
  int b = dir ? x - NB0 : x;
  int oppx = dir ? b : (NB0 + b);
  const int* opp = g_kidx + (size_t)oppx * MM;
  const int* own = g_kidx + (size_t)x * MM;
  const float4* warp = (const float4*)((dir ? wB : wA) + (size_t)b * HWV * 4);
  int t = threadIdx.x;
  for (int i = t; i < MM; i += 128) {
    int id = opp[i]; int hh = id >> 9, ww = id & 511;
    float px = ((float)ww + 0.5f) * (2.0f / (float)WW) - 1.0f;
    float py = ((float)hh + 0.5f) * (2.0f / (float)HH) - 1.0f;
    sp[i] = make_float4(2.0f * px, 2.0f * py, fmaf(px, px, py * py), 0.f);
  }
  __syncthreads();
  int i = seg * 128 + t;
  int id = own[i];
  float4 wp = warp[id];
  float txc = wp.z, tyc = wp.w;
  float m0 = -3.4e38f, m1 = -3.4e38f, m2 = -3.4e38f, m3 = -3.4e38f;
#pragma unroll 2
  for (int j = 0; j < MM; j += 4) {
    float4 p0 = sp[j], p1 = sp[j + 1], p2 = sp[j + 2], p3 = sp[j + 3];
    m0 = fmaxf(m0, fmaf(p0.x, txc, fmaf(p0.y, tyc, -p0.z)));
    m1 = fmaxf(m1, fmaf(p1.x, txc, fmaf(p1.y, tyc, -p1.z)));
    m2 = fmaxf(m2, fmaf(p2.x, txc, fmaf(p2.y, tyc, -p2.z)));
    m3 = fmaxf(m3, fmaf(p3.x, txc, fmaf(p3.y, tyc, -p3.z)));
  }
  float m = fmaxf(fmaxf(m0, m1), fmaxf(m2, m3));
  float dmin = fmaxf(fmaf(txc, txc, tyc * tyc) - m, 0.f);
  float r = expf(-100.0f * sqrtf(dmin + 1e-12f));
  float lse = g_lse[x];
  float contrib = g_slg[(size_t)x * MM + i] ? r * (g_ssl[(size_t)x * MM + i] - lse) : 0.f;
  contrib = blkSum128(contrib, red, t);
  if (t == 0) g_spart[x * 16 + seg] = contrib;
}

// ---------------- final combine ----------------
__global__ __launch_bounds__(256) void k_final(float* __restrict__ out) {
  __shared__ float sZ[128], sS[128], sV[128], sD[128];
  __shared__ float sm[16];
  __shared__ float ssp[256];
  int t = threadIdx.x;
  if (t < 128) {
    int img = t >> 3, seg = t & 7;
    float z = 0.f, s = 0.f, v = 0.f, d = 0.f;
    for (int j = 0; j < 16; j++) {
      const float* p = g_mpart + ((size_t)img * 128 + seg * 16 + j) * 4;
      z += p[0]; s += p[1]; v += p[2]; d += p[3];
    }
    sZ[t] = z; sS[t] = s; sV[t] = v; sD[t] = d;
  }
  ssp[t] = g_spart[t];
  __syncthreads();
  if (t < 16) {
    float z = 0.f, s = 0.f, v = 0.f, d = 0.f;
    for (int seg = 0; seg < 8; seg++) {
      z += sZ[t * 8 + seg]; s += sS[t * 8 + seg];
      v += sV[t * 8 + seg]; d += sD[t * 8 + seg];
    }
    float inv = 1.0f / s;
    sm[t] = inv * (d - v) - logf(s) + logf(z);
  }
  __syncthreads();
  if (t == 0) {
    float sp = 0.f;
    for (int i = 0; i < 256; i++) sp += ssp[i];
    float m = 0.f;
    for (int i = 0; i < 16; i++) m += sm[i];
    out[0] = -sp + m * (1.0f / 16.0f);
  }
}

// ---------------- host launcher ----------------
extern "C" void kernel_launch(void* const* d_in, const int* in_sizes, int n_in,
                              void* d_out, int out_size) {
  (void)in_sizes; (void)n_in; (void)out_size;
  const float* scoremap = (const float*)d_in[0];
  const float* wA = (const float*)d_in[1];
  const float* wB = (const float*)d_in[2];
  const float* vA = (const float*)d_in[3];
  const float* vB = (const float*)d_in[4];
  const float* hd = (const float*)d_in[5];
  float* out = (float*)d_out;

  void* p_a = 0;
  cudaGetSymbolAddress(&p_a, g_t1a);

  dim3 hg(HH / 4, NB);
  dim3 hb(64, 4);
  dim3 vg(WW / 32, HH / 64, NB);
  dim3 cg(WW / 32, HH / 128, NB);
  dim3 vb(32, 8);
  dim3 ng(WW / 32, HH / 32, NB);
  dim3 nb(32, 8);
  dim3 dg(NB, 16);

  k_init<<<1, 32>>>();
  k_hall<<<hg, hb>>>(scoremap, hd);
  k_vmatch<<<vg, vb>>>();
  k_vcov<<<cg, vb>>>(scoremap);
  k_nms5<<<ng, nb>>>((const float*)p_a);
  k_topk<<<NB, 1024>>>(scoremap, vA, vB);
  k_dist<<<dg, 128>>>(wA, wB);
  k_final<<<1, 256>>>(out);
}

// round 7
// speedup vs baseline: 1.1256x; 1.0282x over previous
#include <cuda_runtime.h>
#include <stdint.h>
#include <math.h>

#define HH 512
#define WW 512
#define HWV (HH*WW)
#define NB 16
#define NB0 8
#define MM 2048
#define SCAP 32768

// ---------------- compile-time taps ----------------
__host__ __device__ constexpr double cexp(double x) {
  double y = x < 0 ? -x : x;
  int n = (int)y;
  double f = y - n;
  double term = 1.0, sum = 1.0;
  for (int i = 1; i < 28; i++) { term = term * f / (double)i; sum += term; }
  double en = 1.0;
  for (int i = 0; i < n; i++) en *= 2.71828182845904523536028747135;
  double r = en * sum;
  return x < 0 ? 1.0 / r : r;
}
__host__ __device__ constexpr float gtap(int i) {
  double s = 0.0, gi = 0.0;
  for (int j = 0; j < 25; j++) {
    double xx = -1.0 + 2.0 * (double)j / 24.0;
    double g = cexp(-xx * xx / 0.5);
    if (j == i) gi = g;
    s += g;
  }
  return (float)(gi / s);
}
__host__ __device__ constexpr float wctap(int i) {
  double xx = -2.0 + 4.0 * (double)i / 50.0;
  return (float)cexp(-xx * xx);
}

// scalar scatter (horizontal conv)
template<int K, int KMAX, int Q, int D, int TMAX, int TSEL>
__device__ __forceinline__ void scat(float x, float* acc) {
  if constexpr (K < KMAX) {
    constexpr int t = Q - D - K;
    if constexpr (t >= 0 && t <= TMAX) {
      constexpr float tp = (TSEL == 0) ? gtap((t >= 0 && t <= TMAX) ? t : 0)
                                       : wctap((t >= 0 && t <= TMAX) ? t : 0);
      acc[K] = fmaf(tp, x, acc[K]);
    }
    scat<K + 1, KMAX, Q, D, TMAX, TSEL>(x, acc);
  }
}
template<int G4, int GMAX, int KMAX, int D, int TMAX, int TSEL>
__device__ __forceinline__ void conv4(const float4* w4, float* acc) {
  if constexpr (G4 < GMAX) {
    float4 X = w4[G4];
    scat<0, KMAX, 4 * G4 + 0, D, TMAX, TSEL>(X.x, acc);
    scat<0, KMAX, 4 * G4 + 1, D, TMAX, TSEL>(X.y, acc);
    scat<0, KMAX, 4 * G4 + 2, D, TMAX, TSEL>(X.z, acc);
    scat<0, KMAX, 4 * G4 + 3, D, TMAX, TSEL>(X.w, acc);
    conv4<G4 + 1, GMAX, KMAX, D, TMAX, TSEL>(w4, acc);
  }
}
// float2 scatter (vertical convs, 2 columns/thread)
template<int K, int KMAX, int Q, int TMAX, int TSEL>
__device__ __forceinline__ void scat2(float2 x, float2* acc) {
  if constexpr (K < KMAX) {
    constexpr int t = Q - K;
    if constexpr (t >= 0 && t <= TMAX) {
      constexpr float tp = (TSEL == 0) ? gtap((t >= 0 && t <= TMAX) ? t : 0)
                                       : wctap((t >= 0 && t <= TMAX) ? t : 0);
      acc[K].x = fmaf(tp, x.x, acc[K].x);
      acc[K].y = fmaf(tp, x.y, acc[K].y);
    }
    scat2<K + 1, KMAX, Q, TMAX, TSEL>(x, acc);
  }
}
template<int R, int RMAX, int KMAX, int TMAX, int TSEL, bool CHK>
__device__ __forceinline__ void vloop2(const float2* p, int hlo, float2* acc) {
  if constexpr (R < RMAX) {
    float2 x = make_float2(0.f, 0.f);
    if (!CHK || ((unsigned)(hlo + R) < (unsigned)HH)) x = p[R * (WW / 2)];
    scat2<0, KMAX, R, TMAX, TSEL>(x, acc);
    vloop2<R + 1, RMAX, KMAX, TMAX, TSEL, CHK>(p, hlo, acc);
  }
}
template<int R, int RMAX, bool CHK>
__device__ __forceinline__ void vmloop2(const float2* ps, const float2* pd, int hlo,
                                        float2* as, float2* ad) {
  if constexpr (R < RMAX) {
    float2 xs = make_float2(0.f, 0.f), xd = make_float2(0.f, 0.f);
    if (!CHK || ((unsigned)(hlo + R) < (unsigned)HH)) {
      xs = ps[R * (WW / 2)];
      xd = pd[R * (WW / 2)];
    }
    scat2<0, 8, R, 24, 0>(xs, as);
    scat2<0, 8, R, 24, 0>(xd, ad);
    vmloop2<R + 1, RMAX, CHK>(ps, pd, hlo, as, ad);
  }
}

// ---------------- device scratch ----------------
__device__ float g_WCP[52];
__device__ float g_t1a[NB*HWV];
__device__ float g_t1b[NB*HWV];
__device__ float g_t1c[NB*HWV];
__device__ float g_ps[NB*128];
__device__ float g_mpart[NB*128*4];
__device__ int   g_svcnt[NB];
__device__ float g_svval[NB*SCAP];
__device__ int   g_svidx[NB*SCAP];
__device__ int   g_kidx[NB*MM];
__device__ float g_ssl[NB*MM];
__device__ unsigned char g_slg[NB*MM];
__device__ float g_lse[NB];
__device__ float g_spart[NB*16];

// ---------------- reductions ----------------
__device__ __forceinline__ float blkMax1024(float v, float* red) {
  int t = threadIdx.x;
  red[t] = v; __syncthreads();
  for (int s = 512; s > 0; s >>= 1) {
    if (t < s) red[t] = fmaxf(red[t], red[t + s]);
    __syncthreads();
  }
  float r = red[0]; __syncthreads();
  return r;
}
__device__ __forceinline__ float blkSum1024(float v, float* red) {
  int t = threadIdx.x;
  red[t] = v; __syncthreads();
  for (int s = 512; s > 0; s >>= 1) {
    if (t < s) red[t] += red[t + s];
    __syncthreads();
  }
  float r = red[0]; __syncthreads();
  return r;
}
__device__ __forceinline__ float blkSum256(float v, float* red, int t) {
  red[t] = v; __syncthreads();
  for (int s = 128; s > 0; s >>= 1) {
    if (t < s) red[t] += red[t + s];
    __syncthreads();
  }
  float r = red[0]; __syncthreads();
  return r;
}
__device__ __forceinline__ float blkSum128(float v, float* red, int t) {
  red[t] = v; __syncthreads();
  for (int s = 64; s > 0; s >>= 1) {
    if (t < s) red[t] += red[t + s];
    __syncthreads();
  }
  float r = red[0]; __syncthreads();
  return r;
}

// ---------------- fused horizontal pass (+ init duties) ----------------
__global__ __launch_bounds__(256) void k_hall(const float* __restrict__ score,
                                              const float* __restrict__ hd) {
  __shared__ float sE[4][568];
  __shared__ float sD[4][536];
  __shared__ float red[256];
  int b = blockIdx.y;
  int tx = threadIdx.x, ty = threadIdx.y;    // (64,4)
  int h = blockIdx.x * 4 + ty;
  int tid = ty * 64 + tx;
  if (blockIdx.x == 0 && tid == 0) {
    g_svcnt[b] = 0;
    if (b == 0) {
      float p = 0.f;
      for (int i = 0; i < 51; i++) {
        float x = -2.0f + (4.0f / 50.0f) * (float)i;
        g_WCP[i] = p;
        p += expf(-x * x);
      }
      g_WCP[51] = p;
    }
  }
  const float* srow = score + (size_t)b * HWV + (size_t)h * WW;
  const float* drow = hd + (size_t)b * HWV + (size_t)h * WW;
  float esum = 0.f;
  for (int c = tx; c < 568; c += 64) {
    int w = c - 28;
    float e = 0.f;
    if (w >= 0 && w < WW) e = __expf(srow[w]);
    sE[ty][c] = e;
    esum += e;
  }
  for (int c = tx; c < 536; c += 64) {
    int w = c - 12;
    sD[ty][c] = (w >= 0 && w < WW) ? drow[w] : 0.f;
  }
  __syncthreads();
  int wbase = 8 * tx;
  size_t obase = (size_t)b * HWV + (size_t)h * WW + wbase;
  {
    float acc[8];
#pragma unroll
    for (int k = 0; k < 8; k++) acc[k] = 0.f;
    conv4<0, 16, 8, 3, 50, 1>((const float4*)&sE[ty][wbase], acc);
    float4* o = (float4*)(g_t1c + obase);
    o[0] = make_float4(acc[0], acc[1], acc[2], acc[3]);
    o[1] = make_float4(acc[4], acc[5], acc[6], acc[7]);
  }
  {
    float acc[8];
#pragma unroll
    for (int k = 0; k < 8; k++) acc[k] = 0.f;
    conv4<4, 12, 8, 16, 24, 0>((const float4*)&sE[ty][wbase], acc);
#pragma unroll
    for (int k = 0; k < 8; k++) {
      int w = wbase + k;
      if (w < 12 || w >= WW - 12) acc[k] = 0.f;
    }
    float4* o = (float4*)(g_t1a + obase);
    o[0] = make_float4(acc[0], acc[1], acc[2], acc[3]);
    o[1] = make_float4(acc[4], acc[5], acc[6], acc[7]);
  }
  {
    float acc[8];
#pragma unroll
    for (int k = 0; k < 8; k++) acc[k] = 0.f;
    conv4<0, 8, 8, 0, 24, 0>((const float4*)&sD[ty][wbase], acc);
    float4* o = (float4*)(g_t1b + obase);
    o[0] = make_float4(acc[0], acc[1], acc[2], acc[3]);
    o[1] = make_float4(acc[4], acc[5], acc[6], acc[7]);
  }
  esum = blkSum256(esum, red, tid);
  if (tid == 0) g_ps[b * 128 + blockIdx.x] = esum;
}

// ---------------- fused vertical convs (s + sd) + matchability partials, 2 cols/thread ----------------
__global__ __launch_bounds__(256) void k_vmatch() {
  __shared__ float red[256];
  int b = blockIdx.z;
  int tx = threadIdx.x, ty = threadIdx.y;
  int c2 = blockIdx.x * 32 + tx;          // float2 column index
  int hb = blockIdx.y * 64 + ty * 8;
  int tid = ty * 32 + tx;
  float pv = (tid < 128) ? g_ps[b * 128 + tid] : 0.f;
  float Z = blkSum256(pv, red, tid);
  float invz = 1.0f / Z;
  const float2* ps = (const float2*)(g_t1a + (size_t)b * HWV);
  const float2* pd = (const float2*)(g_t1b + (size_t)b * HWV);
  float2 as[8], ad[8];
#pragma unroll
  for (int k = 0; k < 8; k++) {
    as[k] = make_float2(0.f, 0.f);
    ad[k] = make_float2(0.f, 0.f);
  }
  int hlo = hb - 12;
  const float2* pps = ps + (size_t)hlo * (WW / 2) + c2;
  const float2* ppd = pd + (size_t)hlo * (WW / 2) + c2;
  if (hlo >= 0 && hlo + 31 < HH) vmloop2<0, 32, false>(pps, ppd, hlo, as, ad);
  else                           vmloop2<0, 32, true>(pps, ppd, hlo, as, ad);
  float zsum = 0.f, sdsum = 0.f, sdv = 0.f, sdlsd = 0.f;
#pragma unroll
  for (int k = 0; k < 8; k++) {
#pragma unroll
    for (int c = 0; c < 2; c++) {
      float a = c ? as[k].y : as[k].x;
      float sd = c ? ad[k].y : ad[k].x;
      float s = fmaf(invz, a, 1e-8f);
      zsum += s;
      sdsum += sd;
      if (sd > 0.f) {
        sdv = fmaf(sd, __logf(s), sdv);
        sdlsd = fmaf(sd, __logf(sd), sdlsd);
      }
    }
  }
  zsum = blkSum256(zsum, red, tid);
  sdsum = blkSum256(sdsum, red, tid);
  sdv = blkSum256(sdv, red, tid);
  sdlsd = blkSum256(sdlsd, red, tid);
  if (tid == 0) {
    int bi = blockIdx.y * 8 + blockIdx.x;
    float* p = g_mpart + ((size_t)b * 128 + bi) * 4;
    p[0] = zsum; p[1] = sdsum; p[2] = sdv; p[3] = sdlsd;
  }
}

// ---------------- vertical coverage conv + border correction + reweight, 2 cols/thread ----------------
__global__ __launch_bounds__(256) void k_vcov(const float* __restrict__ score) {
  __shared__ float red[256];
  int b = blockIdx.z;
  int tx = threadIdx.x, ty = threadIdx.y;
  int c2 = blockIdx.x * 32 + tx;
  int w0 = c2 * 2;
  int hb = blockIdx.y * 128 + ty * 16;
  int tid = ty * 32 + tx;
  float pv = (tid < 128) ? g_ps[b * 128 + tid] : 0.f;
  float Z = blkSum256(pv, red, tid);
  float invz = 1.0f / Z;
  const float2* pin = (const float2*)(g_t1c + (size_t)b * HWV);
  float2 acc[16];
#pragma unroll
  for (int k = 0; k < 16; k++) acc[k] = make_float2(0.f, 0.f);
  int hlo = hb - 25;
  const float2* p = pin + (size_t)hlo * (WW / 2) + c2;
  if (hlo >= 0 && hlo + 65 < HH) vloop2<0, 66, 16, 50, 1, false>(p, hlo, acc);
  else                           vloop2<0, 66, 16, 50, 1, true>(p, hlo, acc);
  int jlo0 = (25 - w0 > 0) ? (25 - w0) : 0;
  int jhi0 = (536 - w0 < 50) ? (536 - w0) : 50;
  float Tw0 = g_WCP[jhi0 + 1] - g_WCP[jlo0];
  int w1 = w0 + 1;
  int jlo1 = (25 - w1 > 0) ? (25 - w1) : 0;
  int jhi1 = (536 - w1 < 50) ? (536 - w1) : 50;
  float Tw1 = g_WCP[jhi1 + 1] - g_WCP[jlo1];
  const float2* sc = (const float2*)(score + (size_t)b * HWV);
  float2* po = (float2*)(g_t1a + (size_t)b * HWV);
#pragma unroll
  for (int k = 0; k < 16; k++) {
    int hg = hb + k;
    int ilo = (25 - hg > 0) ? (25 - hg) : 0;
    int ihi = (536 - hg < 50) ? (536 - hg) : 50;
    float Tv = g_WCP[ihi + 1] - g_WCP[ilo];
    float ld0 = 1e4f * (invz * acc[k].x + 1e-6f * Tw0 * Tv);
    float ld1 = 1e4f * (invz * acc[k].y + 1e-6f * Tw1 * Tv);
    size_t oi = (size_t)hg * (WW / 2) + c2;
    float2 s2 = sc[oi];
    po[oi] = make_float2(__expf(s2.x) * invz * rsqrtf(ld0 + 1e-8f),
                         __expf(s2.y) * invz * rsqrtf(ld1 + 1e-8f));
  }
}

// ---------------- fused 5x5 NMS + survivor compaction ----------------
__global__ __launch_bounds__(256) void k_nms5(const float* __restrict__ sm2) {
  __shared__ float sh[36 * 36];
  __shared__ float rm[36 * 32];
  int b = blockIdx.z;
  int h0 = blockIdx.y * 32, w0 = blockIdx.x * 32;
  int t = threadIdx.y * 32 + threadIdx.x;
  const float* img = sm2 + (size_t)b * HWV;
  for (int i = t; i < 36 * 36; i += 256) {
    int r = i / 36, c = i - r * 36;
    int hh = h0 - 2 + r, ww = w0 - 2 + c;
    sh[i] = (hh >= 0 && hh < HH && ww >= 0 && ww < WW) ? img[(size_t)hh * WW + ww] : -INFINITY;
  }
  __syncthreads();
  for (int i = t; i < 36 * 32; i += 256) {
    int r = i >> 5, c = i & 31;
    const float* p = sh + r * 36 + c;
    rm[r * 32 + c] = fmaxf(fmaxf(fmaxf(p[0], p[1]), fmaxf(p[2], p[3])), p[4]);
  }
  __syncthreads();
#pragma unroll
  for (int s = 0; s < 4; s++) {
    int r = threadIdx.y + s * 8;
    int c = threadIdx.x;
    const float* p = rm + r * 32 + c;
    float m = fmaxf(fmaxf(fmaxf(p[0], p[32]), fmaxf(p[64], p[96])), p[128]);
    float val = sh[(r + 2) * 36 + (c + 2)];
    if (val == m) {
      int pp = atomicAdd(&g_svcnt[b], 1);
      if (pp < SCAP) {
        g_svval[(size_t)b * SCAP + pp] = val;
        g_svidx[(size_t)b * SCAP + pp] = (h0 + r) * WW + (w0 + c);
      }
    }
  }
}

// ---------------- top-2048 radix select + gather + masked LSE ----------------
__global__ __launch_bounds__(1024) void k_topk(const float* __restrict__ scoremap,
                                               const float* __restrict__ vA,
                                               const float* __restrict__ vB) {
  int x = blockIdx.x;
  int n = g_svcnt[x]; if (n > SCAP) n = SCAP;
  const float* vals = g_svval + (size_t)x * SCAP;
  const int* idxs = g_svidx + (size_t)x * SCAP;
  int* out = g_kidx + (size_t)x * MM;
  __shared__ int hist[256];
  __shared__ float red[1024];
  __shared__ int sh_k, sh_dig, sh_ngt, sh_neq;
  int t = threadIdx.x;
  unsigned int prefix = 0;
  int k = MM;
  for (int lvl = 0; lvl < 4; lvl++) {
    int shift = 24 - 8 * lvl;
    if (t < 256) hist[t] = 0;
    __syncthreads();
    for (int i = t; i < n; i += 1024) {
      unsigned int u = __float_as_uint(vals[i]);
      bool ok = (lvl == 0) || ((u >> (shift + 8)) == (prefix >> (shift + 8)));
      if (ok) atomicAdd(&hist[(u >> shift) & 255], 1);
    }
    __syncthreads();
    if (t == 0) {
      int acc = 0, d;
      for (d = 255; d >= 0; d--) {
        if (acc + hist[d] >= k) break;
        acc += hist[d];
      }
      if (d < 0) d = 0;
      sh_k = k - acc; sh_dig = d;
    }
    __syncthreads();
    k = sh_k;
    prefix |= ((unsigned int)sh_dig) << shift;
    __syncthreads();
  }
  unsigned int T = prefix;
  if (t == 0) { sh_ngt = 0; sh_neq = 0; }
  __syncthreads();
  for (int i = t; i < n; i += 1024) {
    unsigned int u = __float_as_uint(vals[i]);
    if (u > T) { int p = atomicAdd(&sh_ngt, 1); if (p < MM) out[p] = idxs[i]; }
  }
  __syncthreads();
  int base = sh_ngt;
  for (int i = t; i < n; i += 1024) {
    unsigned int u = __float_as_uint(vals[i]);
    if (u == T) { int p = atomicAdd(&sh_neq, 1); if (base + p < MM) out[base + p] = idxs[i]; }
  }
  __syncthreads();
  int dir = (x >= NB0) ? 1 : 0;
  int b = dir ? x - NB0 : x;
  const float* valid = (dir ? vB : vA) + (size_t)b * HWV;
  const float* logit = scoremap + (size_t)x * HWV;
  float mv = -INFINITY;
  for (int i = t; i < MM; i += 1024) {
    int id = out[i];
    float sl = logit[id];
    unsigned char lg = (valid[id] > 0.f) ? 1 : 0;
    g_ssl[(size_t)x * MM + i] = sl;
    g_slg[(size_t)x * MM + i] = lg;
    mv = fmaxf(mv, lg ? sl : -1e9f);
  }
  mv = blkMax1024(mv, red);
  float z = 0.f;
  for (int i = t; i < MM; i += 1024) {
    float ml = g_slg[(size_t)x * MM + i] ? g_ssl[(size_t)x * MM + i] : -1e9f;
    z += expf(ml - mv);
  }
  z = blkSum1024(z, red);
  if (t == 0) g_lse[x] = mv + logf(z);
}

// ---------------- distance + reward + weighted loss partials ----------------
__global__ __launch_bounds__(128) void k_dist(const float* __restrict__ wA,
                                              const float* __restrict__ wB) {
  __shared__ float4 sp[MM];
  __shared__ float red[128];
  int x = blockIdx.x, seg = blockIdx.y;
  int dir = (x >= NB0) ? 1 : 0;
  int b = dir ? x - NB0 : x;
  int oppx = dir ? b : (NB0 + b);
  const int* opp = g_kidx + (size_t)oppx * MM;
  const int* own = g_kidx + (size_t)x * MM;
  const float4* warp = (const float4*)((dir ? wB : wA) + (size_t)b * HWV * 4);
  int t = threadIdx.x;
  for (int i = t; i < MM; i += 128) {
    int id = opp[i]; int hh = id >> 9, ww = id & 511;
    float px = ((float)ww + 0.5f) * (2.0f / (float)WW) - 1.0f;
    float py = ((float)hh + 0.5f) * (2.0f / (float)HH) - 1.0f;
    sp[i] = make_float4(2.0f * px, 2.0f * py, fmaf(px, px, py * py), 0.f);
  }
  __syncthreads();
  int i = seg * 128 + t;
  int id = own[i];
  float4 wp = warp[id];
  float txc = wp.z, tyc = wp.w;
  float m0 = -3.4e38f, m1 = -3.4e38f, m2 = -3.4e38f, m3 = -3.4e38f;
#pragma unroll 2
  for (int j = 0; j < MM; j += 4) {
    float4 p0 = sp[j], p1 = sp[j + 1], p2 = sp[j + 2], p3 = sp[j + 3];
    m0 = fmaxf(m0, fmaf(p0.x, txc, fmaf(p0.y, tyc, -p0.z)));
    m1 = fmaxf(m1, fmaf(p1.x, txc, fmaf(p1.y, tyc, -p1.z)));
    m2 = fmaxf(m2, fmaf(p2.x, txc, fmaf(p2.y, tyc, -p2.z)));
    m3 = fmaxf(m3, fmaf(p3.x, txc, fmaf(p3.y, tyc, -p3.z)));
  }
  float m = fmaxf(fmaxf(m0, m1), fmaxf(m2, m3));
  float dmin = fmaxf(fmaf(txc, txc, tyc * tyc) - m, 0.f);
  float r = expf(-100.0f * sqrtf(dmin + 1e-12f));
  float lse = g_lse[x];
  float contrib = g_slg[(size_t)x * MM + i] ? r * (g_ssl[(size_t)x * MM + i] - lse) : 0.f;
  contrib = blkSum128(contrib, red, t);
  if (t == 0) g_spart[x * 16 + seg] = contrib;
}

// ---------------- final combine ----------------
__global__ __launch_bounds__(256) void k_final(float* __restrict__ out) {
  __shared__ float sZ[128], sS[128], sV[128], sD[128];
  __shared__ float sm[16];
  __shared__ float ssp[256];
  int t = threadIdx.x;
  if (t < 128) {
    int img = t >> 3, seg = t & 7;
    float z = 0.f, s = 0.f, v = 0.f, d = 0.f;
    for (int j = 0; j < 16; j++) {
      const float* p = g_mpart + ((size_t)img * 128 + seg * 16 + j) * 4;
      z += p[0]; s += p[1]; v += p[2]; d += p[3];
    }
    sZ[t] = z; sS[t] = s; sV[t] = v; sD[t] = d;
  }
  ssp[t] = g_spart[t];
  __syncthreads();
  if (t < 16) {
    float z = 0.f, s = 0.f, v = 0.f, d = 0.f;
    for (int seg = 0; seg < 8; seg++) {
      z += sZ[t * 8 + seg]; s += sS[t * 8 + seg];
      v += sV[t * 8 + seg]; d += sD[t * 8 + seg];
    }
    float inv = 1.0f / s;
    sm[t] = inv * (d - v) - logf(s) + logf(z);
  }
  __syncthreads();
  if (t == 0) {
    float sp = 0.f;
    for (int i = 0; i < 256; i++) sp += ssp[i];
    float m = 0.f;
    for (int i = 0; i < 16; i++) m += sm[i];
    out[0] = -sp + m * (1.0f / 16.0f);
  }
}

// ---------------- host launcher ----------------
extern "C" void kernel_launch(void* const* d_in, const int* in_sizes, int n_in,
                              void* d_out, int out_size) {
  (void)in_sizes; (void)n_in; (void)out_size;
  const float* scoremap = (const float*)d_in[0];
  const float* wA = (const float*)d_in[1];
  const float* wB = (const float*)d_in[2];
  const float* vA = (const float*)d_in[3];
  const float* vB = (const float*)d_in[4];
  const float* hd = (const float*)d_in[5];
  float* out = (float*)d_out;

  void* p_a = 0;
  cudaGetSymbolAddress(&p_a, g_t1a);

  dim3 hg(HH / 4, NB);
  dim3 hb(64, 4);
  dim3 vg(WW / 64, HH / 64, NB);   // 8 x 8 x 16
  dim3 cg(WW / 64, HH / 128, NB);  // 8 x 4 x 16
  dim3 vb(32, 8);
  dim3 ng(WW / 32, HH / 32, NB);
  dim3 nb(32, 8);
  dim3 dg(NB, 16);

  k_hall<<<hg, hb>>>(scoremap, hd);
  k_vmatch<<<vg, vb>>>();
  k_vcov<<<cg, vb>>>(scoremap);
  k_nms5<<<ng, nb>>>((const float*)p_a);
  k_topk<<<NB, 1024>>>(scoremap, vA, vB);
  k_dist<<<dg, 128>>>(wA, wB);
  k_final<<<1, 256>>>(out);
}

// round 8
// speedup vs baseline: 1.4786x; 1.3136x over previous
#include <cuda_runtime.h>
#include <stdint.h>
#include <math.h>

#define HH 512
#define WW 512
#define HWV (HH*WW)
#define NB 16
#define NB0 8
#define MM 2048
#define SCAP 32768

// ---------------- compile-time taps ----------------
__host__ __device__ constexpr double cexp(double x) {
  double y = x < 0 ? -x : x;
  int n = (int)y;
  double f = y - n;
  double term = 1.0, sum = 1.0;
  for (int i = 1; i < 28; i++) { term = term * f / (double)i; sum += term; }
  double en = 1.0;
  for (int i = 0; i < n; i++) en *= 2.71828182845904523536028747135;
  double r = en * sum;
  return x < 0 ? 1.0 / r : r;
}
__host__ __device__ constexpr float gtap(int i) {
  double s = 0.0, gi = 0.0;
  for (int j = 0; j < 25; j++) {
    double xx = -1.0 + 2.0 * (double)j / 24.0;
    double g = cexp(-xx * xx / 0.5);
    if (j == i) gi = g;
    s += g;
  }
  return (float)(gi / s);
}
__host__ __device__ constexpr float wctap(int i) {
  double xx = -2.0 + 4.0 * (double)i / 50.0;
  return (float)cexp(-xx * xx);
}

// scalar scatter (horizontal conv)
template<int K, int KMAX, int Q, int D, int TMAX, int TSEL>
__device__ __forceinline__ void scat(float x, float* acc) {
  if constexpr (K < KMAX) {
    constexpr int t = Q - D - K;
    if constexpr (t >= 0 && t <= TMAX) {
      constexpr float tp = (TSEL == 0) ? gtap((t >= 0 && t <= TMAX) ? t : 0)
                                       : wctap((t >= 0 && t <= TMAX) ? t : 0);
      acc[K] = fmaf(tp, x, acc[K]);
    }
    scat<K + 1, KMAX, Q, D, TMAX, TSEL>(x, acc);
  }
}
template<int G4, int GMAX, int KMAX, int D, int TMAX, int TSEL>
__device__ __forceinline__ void conv4(const float4* w4, float* acc) {
  if constexpr (G4 < GMAX) {
    float4 X = w4[G4];
    scat<0, KMAX, 4 * G4 + 0, D, TMAX, TSEL>(X.x, acc);
    scat<0, KMAX, 4 * G4 + 1, D, TMAX, TSEL>(X.y, acc);
    scat<0, KMAX, 4 * G4 + 2, D, TMAX, TSEL>(X.z, acc);
    scat<0, KMAX, 4 * G4 + 3, D, TMAX, TSEL>(X.w, acc);
    conv4<G4 + 1, GMAX, KMAX, D, TMAX, TSEL>(w4, acc);
  }
}
// float2 scatter (vertical convs, 2 columns/thread)
template<int K, int KMAX, int Q, int TMAX, int TSEL>
__device__ __forceinline__ void scat2(float2 x, float2* acc) {
  if constexpr (K < KMAX) {
    constexpr int t = Q - K;
    if constexpr (t >= 0 && t <= TMAX) {
      constexpr float tp = (TSEL == 0) ? gtap((t >= 0 && t <= TMAX) ? t : 0)
                                       : wctap((t >= 0 && t <= TMAX) ? t : 0);
      acc[K].x = fmaf(tp, x.x, acc[K].x);
      acc[K].y = fmaf(tp, x.y, acc[K].y);
    }
    scat2<K + 1, KMAX, Q, TMAX, TSEL>(x, acc);
  }
}
template<int R, int RMAX, int KMAX, int TMAX, int TSEL, bool CHK>
__device__ __forceinline__ void vloop2(const float2* p, int hlo, float2* acc) {
  if constexpr (R < RMAX) {
    float2 x = make_float2(0.f, 0.f);
    if (!CHK || ((unsigned)(hlo + R) < (unsigned)HH)) x = p[R * (WW / 2)];
    scat2<0, KMAX, R, TMAX, TSEL>(x, acc);
    vloop2<R + 1, RMAX, KMAX, TMAX, TSEL, CHK>(p, hlo, acc);
  }
}
template<int R, int RMAX, bool CHK>
__device__ __forceinline__ void vmloop2(const float2* ps, const float2* pd, int hlo,
                                        float2* as, float2* ad) {
  if constexpr (R < RMAX) {
    float2 xs = make_float2(0.f, 0.f), xd = make_float2(0.f, 0.f);
    if (!CHK || ((unsigned)(hlo + R) < (unsigned)HH)) {
      xs = ps[R * (WW / 2)];
      xd = pd[R * (WW / 2)];
    }
    scat2<0, 8, R, 24, 0>(xs, as);
    scat2<0, 8, R, 24, 0>(xd, ad);
    vmloop2<R + 1, RMAX, CHK>(ps, pd, hlo, as, ad);
  }
}

// ---------------- device scratch ----------------
__device__ float g_WCP[52];
__device__ float g_t1a[NB*HWV];
__device__ float g_t1b[NB*HWV];
__device__ float g_t1c[NB*HWV];
__device__ float g_ps[NB*128];
__device__ float g_mpart[NB*128*4];
__device__ int   g_svcnt[NB];
__device__ float g_svval[NB*SCAP];
__device__ int   g_svidx[NB*SCAP];
__device__ int   g_kidx[NB*MM];
__device__ float g_ssl[NB*MM];
__device__ unsigned char g_slg[NB*MM];
__device__ float g_lse[NB];
__device__ float g_spart[NB*16];

// ---------------- reductions ----------------
__device__ __forceinline__ float blkMax1024(float v, float* red) {
  int t = threadIdx.x;
  red[t] = v; __syncthreads();
  for (int s = 512; s > 0; s >>= 1) {
    if (t < s) red[t] = fmaxf(red[t], red[t + s]);
    __syncthreads();
  }
  float r = red[0]; __syncthreads();
  return r;
}
__device__ __forceinline__ float blkSum1024(float v, float* red) {
  int t = threadIdx.x;
  red[t] = v; __syncthreads();
  for (int s = 512; s > 0; s >>= 1) {
    if (t < s) red[t] += red[t + s];
    __syncthreads();
  }
  float r = red[0]; __syncthreads();
  return r;
}
__device__ __forceinline__ float blkSum256(float v, float* red, int t) {
  red[t] = v; __syncthreads();
  for (int s = 128; s > 0; s >>= 1) {
    if (t < s) red[t] += red[t + s];
    __syncthreads();
  }
  float r = red[0]; __syncthreads();
  return r;
}
__device__ __forceinline__ float blkSum128(float v, float* red, int t) {
  red[t] = v; __syncthreads();
  for (int s = 64; s > 0; s >>= 1) {
    if (t < s) red[t] += red[t + s];
    __syncthreads();
  }
  float r = red[0]; __syncthreads();
  return r;
}

// ---------------- fused horizontal pass (+ init duties) ----------------
__global__ __launch_bounds__(256) void k_hall(const float* __restrict__ score,
                                              const float* __restrict__ hd) {
  __shared__ float sE[4][568];
  __shared__ float sD[4][536];
  __shared__ float red[256];
  int b = blockIdx.y;
  int tx = threadIdx.x, ty = threadIdx.y;    // (64,4)
  int h = blockIdx.x * 4 + ty;
  int tid = ty * 64 + tx;
  if (blockIdx.x == 0 && tid == 0) {
    g_svcnt[b] = 0;
    if (b == 0) {
      float p = 0.f;
      for (int i = 0; i < 51; i++) {
        float x = -2.0f + (4.0f / 50.0f) * (float)i;
        g_WCP[i] = p;
        p += expf(-x * x);
      }
      g_WCP[51] = p;
    }
  }
  const float* srow = score + (size_t)b * HWV + (size_t)h * WW;
  const float* drow = hd + (size_t)b * HWV + (size_t)h * WW;
  float esum = 0.f;
  for (int c = tx; c < 568; c += 64) {
    int w = c - 28;
    float e = 0.f;
    if (w >= 0 && w < WW) e = __expf(srow[w]);
    sE[ty][c] = e;
    esum += e;
  }
  for (int c = tx; c < 536; c += 64) {
    int w = c - 12;
    sD[ty][c] = (w >= 0 && w < WW) ? drow[w] : 0.f;
  }
  __syncthreads();
  int wbase = 8 * tx;
  size_t obase = (size_t)b * HWV + (size_t)h * WW + wbase;
  {
    float acc[8];
#pragma unroll
    for (int k = 0; k < 8; k++) acc[k] = 0.f;
    conv4<0, 16, 8, 3, 50, 1>((const float4*)&sE[ty][wbase], acc);
    float4* o = (float4*)(g_t1c + obase);
    o[0] = make_float4(acc[0], acc[1], acc[2], acc[3]);
    o[1] = make_float4(acc[4], acc[5], acc[6], acc[7]);
  }
  {
    float acc[8];
#pragma unroll
    for (int k = 0; k < 8; k++) acc[k] = 0.f;
    conv4<4, 12, 8, 16, 24, 0>((const float4*)&sE[ty][wbase], acc);
#pragma unroll
    for (int k = 0; k < 8; k++) {
      int w = wbase + k;
      if (w < 12 || w >= WW - 12) acc[k] = 0.f;
    }
    float4* o = (float4*)(g_t1a + obase);
    o[0] = make_float4(acc[0], acc[1], acc[2], acc[3]);
    o[1] = make_float4(acc[4], acc[5], acc[6], acc[7]);
  }
  {
    float acc[8];
#pragma unroll
    for (int k = 0; k < 8; k++) acc[k] = 0.f;
    conv4<0, 8, 8, 0, 24, 0>((const float4*)&sD[ty][wbase], acc);
    float4* o = (float4*)(g_t1b + obase);
    o[0] = make_float4(acc[0], acc[1], acc[2], acc[3]);
    o[1] = make_float4(acc[4], acc[5], acc[6], acc[7]);
  }
  esum = blkSum256(esum, red, tid);
  if (tid == 0) g_ps[b * 128 + blockIdx.x] = esum;
}

// ---------------- fused vertical convs (s + sd) + matchability partials ----------------
__global__ __launch_bounds__(256) void k_vmatch() {
  __shared__ float red[256];
  int b = blockIdx.z;
  int tx = threadIdx.x, ty = threadIdx.y;
  int c2 = blockIdx.x * 32 + tx;
  int hb = blockIdx.y * 64 + ty * 8;
  int tid = ty * 32 + tx;
  float pv = (tid < 128) ? g_ps[b * 128 + tid] : 0.f;
  float Z = blkSum256(pv, red, tid);
  float invz = 1.0f / Z;
  const float2* ps = (const float2*)(g_t1a + (size_t)b * HWV);
  const float2* pd = (const float2*)(g_t1b + (size_t)b * HWV);
  float2 as[8], ad[8];
#pragma unroll
  for (int k = 0; k < 8; k++) {
    as[k] = make_float2(0.f, 0.f);
    ad[k] = make_float2(0.f, 0.f);
  }
  int hlo = hb - 12;
  const float2* pps = ps + (size_t)hlo * (WW / 2) + c2;
  const float2* ppd = pd + (size_t)hlo * (WW / 2) + c2;
  if (hlo >= 0 && hlo + 31 < HH) vmloop2<0, 32, false>(pps, ppd, hlo, as, ad);
  else                           vmloop2<0, 32, true>(pps, ppd, hlo, as, ad);
  float zsum = 0.f, sdsum = 0.f, sdv = 0.f, sdlsd = 0.f;
#pragma unroll
  for (int k = 0; k < 8; k++) {
#pragma unroll
    for (int c = 0; c < 2; c++) {
      float a = c ? as[k].y : as[k].x;
      float sd = c ? ad[k].y : ad[k].x;
      float s = fmaf(invz, a, 1e-8f);
      zsum += s;
      sdsum += sd;
      if (sd > 0.f) {
        sdv = fmaf(sd, __logf(s), sdv);
        sdlsd = fmaf(sd, __logf(sd), sdlsd);
      }
    }
  }
  zsum = blkSum256(zsum, red, tid);
  sdsum = blkSum256(sdsum, red, tid);
  sdv = blkSum256(sdv, red, tid);
  sdlsd = blkSum256(sdlsd, red, tid);
  if (tid == 0) {
    int bi = blockIdx.y * 8 + blockIdx.x;
    float* p = g_mpart + ((size_t)b * 128 + bi) * 4;
    p[0] = zsum; p[1] = sdsum; p[2] = sdv; p[3] = sdlsd;
  }
}

// ---------------- vertical coverage conv + border correction + reweight ----------------
__global__ __launch_bounds__(256) void k_vcov(const float* __restrict__ score) {
  __shared__ float red[256];
  int b = blockIdx.z;
  int tx = threadIdx.x, ty = threadIdx.y;
  int c2 = blockIdx.x * 32 + tx;
  int w0 = c2 * 2;
  int hb = blockIdx.y * 128 + ty * 16;
  int tid = ty * 32 + tx;
  float pv = (tid < 128) ? g_ps[b * 128 + tid] : 0.f;
  float Z = blkSum256(pv, red, tid);
  float invz = 1.0f / Z;
  const float2* pin = (const float2*)(g_t1c + (size_t)b * HWV);
  float2 acc[16];
#pragma unroll
  for (int k = 0; k < 16; k++) acc[k] = make_float2(0.f, 0.f);
  int hlo = hb - 25;
  const float2* p = pin + (size_t)hlo * (WW / 2) + c2;
  if (hlo >= 0 && hlo + 65 < HH) vloop2<0, 66, 16, 50, 1, false>(p, hlo, acc);
  else                           vloop2<0, 66, 16, 50, 1, true>(p, hlo, acc);
  int jlo0 = (25 - w0 > 0) ? (25 - w0) : 0;
  int jhi0 = (536 - w0 < 50) ? (536 - w0) : 50;
  float Tw0 = g_WCP[jhi0 + 1] - g_WCP[jlo0];
  int w1 = w0 + 1;
  int jlo1 = (25 - w1 > 0) ? (25 - w1) : 0;
  int jhi1 = (536 - w1 < 50) ? (536 - w1) : 50;
  float Tw1 = g_WCP[jhi1 + 1] - g_WCP[jlo1];
  const float2* sc = (const float2*)(score + (size_t)b * HWV);
  float2* po = (float2*)(g_t1a + (size_t)b * HWV);
#pragma unroll
  for (int k = 0; k < 16; k++) {
    int hg = hb + k;
    int ilo = (25 - hg > 0) ? (25 - hg) : 0;
    int ihi = (536 - hg < 50) ? (536 - hg) : 50;
    float Tv = g_WCP[ihi + 1] - g_WCP[ilo];
    float ld0 = 1e4f * (invz * acc[k].x + 1e-6f * Tw0 * Tv);
    float ld1 = 1e4f * (invz * acc[k].y + 1e-6f * Tw1 * Tv);
    size_t oi = (size_t)hg * (WW / 2) + c2;
    float2 s2 = sc[oi];
    po[oi] = make_float2(__expf(s2.x) * invz * rsqrtf(ld0 + 1e-8f),
                         __expf(s2.y) * invz * rsqrtf(ld1 + 1e-8f));
  }
}

// ---------------- fused 5x5 NMS + block-aggregated survivor compaction ----------------
__global__ __launch_bounds__(256) void k_nms5(const float* __restrict__ sm2) {
  __shared__ float sh[36 * 36];
  __shared__ float rm[36 * 32];
  __shared__ int scnt, sbase;
  int b = blockIdx.z;
  int h0 = blockIdx.y * 32, w0 = blockIdx.x * 32;
  int t = threadIdx.y * 32 + threadIdx.x;
  if (t == 0) scnt = 0;
  const float* img = sm2 + (size_t)b * HWV;
  for (int i = t; i < 36 * 36; i += 256) {
    int r = i / 36, c = i - r * 36;
    int hh = h0 - 2 + r, ww = w0 - 2 + c;
    sh[i] = (hh >= 0 && hh < HH && ww >= 0 && ww < WW) ? img[(size_t)hh * WW + ww] : -INFINITY;
  }
  __syncthreads();
  for (int i = t; i < 36 * 32; i += 256) {
    int r = i >> 5, c = i & 31;
    const float* p = sh + r * 36 + c;
    rm[r * 32 + c] = fmaxf(fmaxf(fmaxf(p[0], p[1]), fmaxf(p[2], p[3])), p[4]);
  }
  __syncthreads();
  // collect this thread's survivors (up to 4) in registers
  float mv[4]; int mi[4]; int mine = 0;
#pragma unroll
  for (int s = 0; s < 4; s++) {
    int r = threadIdx.y + s * 8;
    int c = threadIdx.x;
    const float* p = rm + r * 32 + c;
    float m = fmaxf(fmaxf(fmaxf(p[0], p[32]), fmaxf(p[64], p[96])), p[128]);
    float val = sh[(r + 2) * 36 + (c + 2)];
    if (val == m) {
      mv[mine] = val;
      mi[mine] = (h0 + r) * WW + (w0 + c);
      mine++;
    }
  }
  int loc = 0;
  if (mine) loc = atomicAdd(&scnt, mine);
  __syncthreads();
  if (t == 0) sbase = atomicAdd(&g_svcnt[b], scnt);
  __syncthreads();
  int base = sbase + loc;
  for (int i = 0; i < mine; i++) {
    int pp = base + i;
    if (pp < SCAP) {
      g_svval[(size_t)b * SCAP + pp] = mv[i];
      g_svidx[(size_t)b * SCAP + pp] = mi[i];
    }
  }
}

// ---------------- top-2048 radix select + gather + masked LSE ----------------
__global__ __launch_bounds__(1024) void k_topk(const float* __restrict__ scoremap,
                                               const float* __restrict__ vA,
                                               const float* __restrict__ vB) {
  int x = blockIdx.x;
  int n = g_svcnt[x]; if (n > SCAP) n = SCAP;
  const float* vals = g_svval + (size_t)x * SCAP;
  const int* idxs = g_svidx + (size_t)x * SCAP;
  int* out = g_kidx + (size_t)x * MM;
  __shared__ int hist[256];
  __shared__ float red[1024];
  __shared__ int sh_k, sh_dig, sh_ngt, sh_neq;
  int t = threadIdx.x;
  unsigned int prefix = 0;
  int k = MM;
  for (int lvl = 0; lvl < 4; lvl++) {
    int shift = 24 - 8 * lvl;
    if (t < 256) hist[t] = 0;
    __syncthreads();
    for (int i = t; i < n; i += 1024) {
      unsigned int u = __float_as_uint(vals[i]);
      bool ok = (lvl == 0) || ((u >> (shift + 8)) == (prefix >> (shift + 8)));
      if (ok) atomicAdd(&hist[(u >> shift) & 255], 1);
    }
    __syncthreads();
    if (t == 0) {
      int acc = 0, d;
      for (d = 255; d >= 0; d--) {
        if (acc + hist[d] >= k) break;
        acc += hist[d];
      }
      if (d < 0) d = 0;
      sh_k = k - acc; sh_dig = d;
    }
    __syncthreads();
    k = sh_k;
    prefix |= ((unsigned int)sh_dig) << shift;
    __syncthreads();
  }
  unsigned int T = prefix;
  if (t == 0) { sh_ngt = 0; sh_neq = 0; }
  __syncthreads();
  for (int i = t; i < n; i += 1024) {
    unsigned int u = __float_as_uint(vals[i]);
    if (u > T) { int p = atomicAdd(&sh_ngt, 1); if (p < MM) out[p] = idxs[i]; }
  }
  __syncthreads();
  int base = sh_ngt;
  for (int i = t; i < n; i += 1024) {
    unsigned int u = __float_as_uint(vals[i]);
    if (u == T) { int p = atomicAdd(&sh_neq, 1); if (base + p < MM) out[base + p] = idxs[i]; }
  }
  __syncthreads();
  int dir = (x >= NB0) ? 1 : 0;
  int b = dir ? x - NB0 : x;
  const float* valid = (dir ? vB : vA) + (size_t)b * HWV;
  const float* logit = scoremap + (size_t)x * HWV;
  float mv = -INFINITY;
  for (int i = t; i < MM; i += 1024) {
    int id = out[i];
    float sl = logit[id];
    unsigned char lg = (valid[id] > 0.f) ? 1 : 0;
    g_ssl[(size_t)x * MM + i] = sl;
    g_slg[(size_t)x * MM + i] = lg;
    mv = fmaxf(mv, lg ? sl : -1e9f);
  }
  mv = blkMax1024(mv, red);
  float z = 0.f;
  for (int i = t; i < MM; i += 1024) {
    float ml = g_slg[(size_t)x * MM + i] ? g_ssl[(size_t)x * MM + i] : -1e9f;
    z += expf(ml - mv);
  }
  z = blkSum1024(z, red);
  if (t == 0) g_lse[x] = mv + logf(z);
}

// ---------------- distance + reward + weighted loss partials ----------------
__global__ __launch_bounds__(128) void k_dist(const float* __restrict__ wA,
                                              const float* __restrict__ wB) {
  __shared__ float4 sp[MM];
  __shared__ float red[128];
  int x = blockIdx.x, seg = blockIdx.y;
  int dir = (x >= NB0) ? 1 : 0;
  int b = dir ? x - NB0 : x;
  int oppx = dir ? b : (NB0 + b);
  const int* opp = g_kidx + (size_t)oppx * MM;
  const int* own = g_kidx + (size_t)x * MM;
  const float4* warp = (const float4*)((dir ? wB : wA) + (size_t)b * HWV * 4);
  int t = threadIdx.x;
  for (int i = t; i < MM; i += 128) {
    int id = opp[i]; int hh = id >> 9, ww = id & 511;
    float px = ((float)ww + 0.5f) * (2.0f / (float)WW) - 1.0f;
    float py = ((float)hh + 0.5f) * (2.0f / (float)HH) - 1.0f;
    sp[i] = make_float4(2.0f * px, 2.0f * py, fmaf(px, px, py * py), 0.f);
  }
  __syncthreads();
  int i = seg * 128 + t;
  int id = own[i];
  float4 wp = warp[id];
  float txc = wp.z, tyc = wp.w;
  float m0 = -3.4e38f, m1 = -3.4e38f, m2 = -3.4e38f, m3 = -3.4e38f;
#pragma unroll 2
  for (int j = 0; j < MM; j += 4) {
    float4 p0 = sp[j], p1 = sp[j + 1], p2 = sp[j + 2], p3 = sp[j + 3];
    m0 = fmaxf(m0, fmaf(p0.x, txc, fmaf(p0.y, tyc, -p0.z)));
    m1 = fmaxf(m1, fmaf(p1.x, txc, fmaf(p1.y, tyc, -p1.z)));
    m2 = fmaxf(m2, fmaf(p2.x, txc, fmaf(p2.y, tyc, -p2.z)));
    m3 = fmaxf(m3, fmaf(p3.x, txc, fmaf(p3.y, tyc, -p3.z)));
  }
  float m = fmaxf(fmaxf(m0, m1), fmaxf(m2, m3));
  float dmin = fmaxf(fmaf(txc, txc, tyc * tyc) - m, 0.f);
  float r = expf(-100.0f * sqrtf(dmin + 1e-12f));
  float lse = g_lse[x];
  float contrib = g_slg[(size_t)x * MM + i] ? r * (g_ssl[(size_t)x * MM + i] - lse) : 0.f;
  contrib = blkSum128(contrib, red, t);
  if (t == 0) g_spart[x * 16 + seg] = contrib;
}

// ---------------- final combine ----------------
__global__ __launch_bounds__(256) void k_final(float* __restrict__ out) {
  __shared__ float sZ[128], sS[128], sV[128], sD[128];
  __shared__ float sm[16];
  __shared__ float ssp[256];
  int t = threadIdx.x;
  if (t < 128) {
    int img = t >> 3, seg = t & 7;
    float z = 0.f, s = 0.f, v = 0.f, d = 0.f;
    for (int j = 0; j < 16; j++) {
      const float* p = g_mpart + ((size_t)img * 128 + seg * 16 + j) * 4;
      z += p[0]; s += p[1]; v += p[2]; d += p[3];
    }
    sZ[t] = z; sS[t] = s; sV[t] = v; sD[t] = d;
  }
  ssp[t] = g_spart[t];
  __syncthreads();
  if (t < 16) {
    float z = 0.f, s = 0.f, v = 0.f, d = 0.f;
    for (int seg = 0; seg < 8; seg++) {
      z += sZ[t * 8 + seg]; s += sS[t * 8 + seg];
      v += sV[t * 8 + seg]; d += sD[t * 8 + seg];
    }
    float inv = 1.0f / s;
    sm[t] = inv * (d - v) - logf(s) + logf(z);
  }
  __syncthreads();
  if (t == 0) {
    float sp = 0.f;
    for (int i = 0; i < 256; i++) sp += ssp[i];
    float m = 0.f;
    for (int i = 0; i < 16; i++) m += sm[i];
    out[0] = -sp + m * (1.0f / 16.0f);
  }
}

// ---------------- host launcher ----------------
extern "C" void kernel_launch(void* const* d_in, const int* in_sizes, int n_in,
                              void* d_out, int out_size) {
  (void)in_sizes; (void)n_in; (void)out_size;
  const float* scoremap = (const float*)d_in[0];
  const float* wA = (const float*)d_in[1];
  const float* wB = (const float*)d_in[2];
  const float* vA = (const float*)d_in[3];
  const float* vB = (const float*)d_in[4];
  const float* hd = (const float*)d_in[5];
  float* out = (float*)d_out;

  void* p_a = 0;
  cudaGetSymbolAddress(&p_a, g_t1a);

  dim3 hg(HH / 4, NB);
  dim3 hb(64, 4);
  dim3 vg(WW / 64, HH / 64, NB);
  dim3 cg(WW / 64, HH / 128, NB);
  dim3 vb(32, 8);
  dim3 ng(WW / 32, HH / 32, NB);
  dim3 nb(32, 8);
  dim3 dg(NB, 16);

  k_hall<<<hg, hb>>>(scoremap, hd);
  k_vmatch<<<vg, vb>>>();
  k_vcov<<<cg, vb>>>(scoremap);
  k_nms5<<<ng, nb>>>((const float*)p_a);
  k_topk<<<NB, 1024>>>(scoremap, vA, vB);
  k_dist<<<dg, 128>>>(wA, wB);
  k_final<<<1, 256>>>(out);
}

// round 9
// speedup vs baseline: 1.6713x; 1.1304x over previous
#include <cuda_runtime.h>
#include <stdint.h>
#include <math.h>

#define HH 512
#define WW 512
#define HWV (HH*WW)
#define NB 16
#define NB0 8
#define MM 2048
#define SCAP 32768

// ---------------- compile-time taps ----------------
__host__ __device__ constexpr double cexp(double x) {
  double y = x < 0 ? -x : x;
  int n = (int)y;
  double f = y - n;
  double term = 1.0, sum = 1.0;
  for (int i = 1; i < 28; i++) { term = term * f / (double)i; sum += term; }
  double en = 1.0;
  for (int i = 0; i < n; i++) en *= 2.71828182845904523536028747135;
  double r = en * sum;
  return x < 0 ? 1.0 / r : r;
}
__host__ __device__ constexpr float gtap(int i) {
  double s = 0.0, gi = 0.0;
  for (int j = 0; j < 25; j++) {
    double xx = -1.0 + 2.0 * (double)j / 24.0;
    double g = cexp(-xx * xx / 0.5);
    if (j == i) gi = g;
    s += g;
  }
  return (float)(gi / s);
}
__host__ __device__ constexpr float wctap(int i) {
  double xx = -2.0 + 4.0 * (double)i / 50.0;
  return (float)cexp(-xx * xx);
}

// scalar scatter (horizontal conv)
template<int K, int KMAX, int Q, int D, int TMAX, int TSEL>
__device__ __forceinline__ void scat(float x, float* acc) {
  if constexpr (K < KMAX) {
    constexpr int t = Q - D - K;
    if constexpr (t >= 0 && t <= TMAX) {
      constexpr float tp = (TSEL == 0) ? gtap((t >= 0 && t <= TMAX) ? t : 0)
                                       : wctap((t >= 0 && t <= TMAX) ? t : 0);
      acc[K] = fmaf(tp, x, acc[K]);
    }
    scat<K + 1, KMAX, Q, D, TMAX, TSEL>(x, acc);
  }
}
template<int G4, int GMAX, int KMAX, int D, int TMAX, int TSEL>
__device__ __forceinline__ void conv4(const float4* w4, float* acc) {
  if constexpr (G4 < GMAX) {
    float4 X = w4[G4];
    scat<0, KMAX, 4 * G4 + 0, D, TMAX, TSEL>(X.x, acc);
    scat<0, KMAX, 4 * G4 + 1, D, TMAX, TSEL>(X.y, acc);
    scat<0, KMAX, 4 * G4 + 2, D, TMAX, TSEL>(X.z, acc);
    scat<0, KMAX, 4 * G4 + 3, D, TMAX, TSEL>(X.w, acc);
    conv4<G4 + 1, GMAX, KMAX, D, TMAX, TSEL>(w4, acc);
  }
}
// float2 scatter (vertical convs)
template<int K, int KMAX, int Q, int TMAX, int TSEL>
__device__ __forceinline__ void scat2(float2 x, float2* acc) {
  if constexpr (K < KMAX) {
    constexpr int t = Q - K;
    if constexpr (t >= 0 && t <= TMAX) {
      constexpr float tp = (TSEL == 0) ? gtap((t >= 0 && t <= TMAX) ? t : 0)
                                       : wctap((t >= 0 && t <= TMAX) ? t : 0);
      acc[K].x = fmaf(tp, x.x, acc[K].x);
      acc[K].y = fmaf(tp, x.y, acc[K].y);
    }
    scat2<K + 1, KMAX, Q, TMAX, TSEL>(x, acc);
  }
}
template<int R, int RMAX, int KMAX, int TMAX, int TSEL, bool CHK>
__device__ __forceinline__ void vloop2(const float2* p, int hlo, float2* acc) {
  if constexpr (R < RMAX) {
    float2 x = make_float2(0.f, 0.f);
    if (!CHK || ((unsigned)(hlo + R) < (unsigned)HH)) x = p[R * (WW / 2)];
    scat2<0, KMAX, R, TMAX, TSEL>(x, acc);
    vloop2<R + 1, RMAX, KMAX, TMAX, TSEL, CHK>(p, hlo, acc);
  }
}
template<int R, int RMAX, bool CHK>
__device__ __forceinline__ void vmloop2(const float2* ps, const float2* pd, int hlo,
                                        float2* as, float2* ad) {
  if constexpr (R < RMAX) {
    float2 xs = make_float2(0.f, 0.f), xd = make_float2(0.f, 0.f);
    if (!CHK || ((unsigned)(hlo + R) < (unsigned)HH)) {
      xs = ps[R * (WW / 2)];
      xd = pd[R * (WW / 2)];
    }
    scat2<0, 8, R, 24, 0>(xs, as);
    scat2<0, 8, R, 24, 0>(xd, ad);
    vmloop2<R + 1, RMAX, CHK>(ps, pd, hlo, as, ad);
  }
}

// ---------------- device scratch ----------------
__device__ float g_WCP[52];
__device__ float g_t1a[NB*HWV];
__device__ float g_t1b[NB*HWV];
__device__ float g_t1c[NB*HWV];
__device__ float g_ps[NB*128];
__device__ float g_mpart[NB*128*4];
__device__ int   g_svcnt[NB];
__device__ float g_svval[NB*SCAP];
__device__ int   g_svidx[NB*SCAP];
__device__ int   g_kidx[NB*MM];
__device__ float g_ssl[NB*MM];
__device__ unsigned char g_slg[NB*MM];
__device__ float g_lse[NB];
__device__ float g_spart[NB*8];

// ---------------- reductions ----------------
__device__ __forceinline__ float blkMax1024(float v, float* red) {
  int t = threadIdx.x;
  red[t] = v; __syncthreads();
  for (int s = 512; s > 0; s >>= 1) {
    if (t < s) red[t] = fmaxf(red[t], red[t + s]);
    __syncthreads();
  }
  float r = red[0]; __syncthreads();
  return r;
}
__device__ __forceinline__ float blkSum1024(float v, float* red) {
  int t = threadIdx.x;
  red[t] = v; __syncthreads();
  for (int s = 512; s > 0; s >>= 1) {
    if (t < s) red[t] += red[t + s];
    __syncthreads();
  }
  float r = red[0]; __syncthreads();
  return r;
}
__device__ __forceinline__ float blkSum256(float v, float* red, int t) {
  red[t] = v; __syncthreads();
  for (int s = 128; s > 0; s >>= 1) {
    if (t < s) red[t] += red[t + s];
    __syncthreads();
  }
  float r = red[0]; __syncthreads();
  return r;
}
__device__ __forceinline__ float blkSum128(float v, float* red, int t) {
  red[t] = v; __syncthreads();
  for (int s = 64; s > 0; s >>= 1) {
    if (t < s) red[t] += red[t + s];
    __syncthreads();
  }
  float r = red[0]; __syncthreads();
  return r;
}

// ---------------- fused horizontal pass (+ init duties) ----------------
__global__ __launch_bounds__(256) void k_hall(const float* __restrict__ score,
                                              const float* __restrict__ hd) {
  __shared__ float sE[4][568];
  __shared__ float sD[4][536];
  __shared__ float red[256];
  int b = blockIdx.y;
  int tx = threadIdx.x, ty = threadIdx.y;    // (64,4)
  int h = blockIdx.x * 4 + ty;
  int tid = ty * 64 + tx;
  if (blockIdx.x == 0 && tid == 0) {
    g_svcnt[b] = 0;
    if (b == 0) {
      float p = 0.f;
      for (int i = 0; i < 51; i++) {
        float x = -2.0f + (4.0f / 50.0f) * (float)i;
        g_WCP[i] = p;
        p += expf(-x * x);
      }
      g_WCP[51] = p;
    }
  }
  const float* srow = score + (size_t)b * HWV + (size_t)h * WW;
  const float* drow = hd + (size_t)b * HWV + (size_t)h * WW;
  float esum = 0.f;
  for (int c = tx; c < 568; c += 64) {
    int w = c - 28;
    float e = 0.f;
    if (w >= 0 && w < WW) e = __expf(srow[w]);
    sE[ty][c] = e;
    esum += e;
  }
  for (int c = tx; c < 536; c += 64) {
    int w = c - 12;
    sD[ty][c] = (w >= 0 && w < WW) ? drow[w] : 0.f;
  }
  __syncthreads();
  int wbase = 8 * tx;
  size_t obase = (size_t)b * HWV + (size_t)h * WW + wbase;
  {
    float acc[8];
#pragma unroll
    for (int k = 0; k < 8; k++) acc[k] = 0.f;
    conv4<0, 16, 8, 3, 50, 1>((const float4*)&sE[ty][wbase], acc);
    float4* o = (float4*)(g_t1c + obase);
    o[0] = make_float4(acc[0], acc[1], acc[2], acc[3]);
    o[1] = make_float4(acc[4], acc[5], acc[6], acc[7]);
  }
  {
    float acc[8];
#pragma unroll
    for (int k = 0; k < 8; k++) acc[k] = 0.f;
    conv4<4, 12, 8, 16, 24, 0>((const float4*)&sE[ty][wbase], acc);
#pragma unroll
    for (int k = 0; k < 8; k++) {
      int w = wbase + k;
      if (w < 12 || w >= WW - 12) acc[k] = 0.f;
    }
    float4* o = (float4*)(g_t1a + obase);
    o[0] = make_float4(acc[0], acc[1], acc[2], acc[3]);
    o[1] = make_float4(acc[4], acc[5], acc[6], acc[7]);
  }
  {
    float acc[8];
#pragma unroll
    for (int k = 0; k < 8; k++) acc[k] = 0.f;
    conv4<0, 8, 8, 0, 24, 0>((const float4*)&sD[ty][wbase], acc);
    float4* o = (float4*)(g_t1b + obase);
    o[0] = make_float4(acc[0], acc[1], acc[2], acc[3]);
    o[1] = make_float4(acc[4], acc[5], acc[6], acc[7]);
  }
  esum = blkSum256(esum, red, tid);
  if (tid == 0) g_ps[b * 128 + blockIdx.x] = esum;
}

// ---------------- fused vertical convs (s + sd) + matchability partials ----------------
__global__ __launch_bounds__(256) void k_vmatch() {
  __shared__ float red[256];
  int b = blockIdx.z;
  int tx = threadIdx.x, ty = threadIdx.y;
  int c2 = blockIdx.x * 32 + tx;
  int hb = blockIdx.y * 64 + ty * 8;
  int tid = ty * 32 + tx;
  float pv = (tid < 128) ? g_ps[b * 128 + tid] : 0.f;
  float Z = blkSum256(pv, red, tid);
  float invz = 1.0f / Z;
  const float2* ps = (const float2*)(g_t1a + (size_t)b * HWV);
  const float2* pd = (const float2*)(g_t1b + (size_t)b * HWV);
  float2 as[8], ad[8];
#pragma unroll
  for (int k = 0; k < 8; k++) {
    as[k] = make_float2(0.f, 0.f);
    ad[k] = make_float2(0.f, 0.f);
  }
  int hlo = hb - 12;
  const float2* pps = ps + (size_t)hlo * (WW / 2) + c2;
  const float2* ppd = pd + (size_t)hlo * (WW / 2) + c2;
  if (hlo >= 0 && hlo + 31 < HH) vmloop2<0, 32, false>(pps, ppd, hlo, as, ad);
  else                           vmloop2<0, 32, true>(pps, ppd, hlo, as, ad);
  float zsum = 0.f, sdsum = 0.f, sdv = 0.f, sdlsd = 0.f;
#pragma unroll
  for (int k = 0; k < 8; k++) {
#pragma unroll
    for (int c = 0; c < 2; c++) {
      float a = c ? as[k].y : as[k].x;
      float sd = c ? ad[k].y : ad[k].x;
      float s = fmaf(invz, a, 1e-8f);
      zsum += s;
      sdsum += sd;
      if (sd > 0.f) {
        sdv = fmaf(sd, __logf(s), sdv);
        sdlsd = fmaf(sd, __logf(sd), sdlsd);
      }
    }
  }
  zsum = blkSum256(zsum, red, tid);
  sdsum = blkSum256(sdsum, red, tid);
  sdv = blkSum256(sdv, red, tid);
  sdlsd = blkSum256(sdlsd, red, tid);
  if (tid == 0) {
    int bi = blockIdx.y * 8 + blockIdx.x;
    float* p = g_mpart + ((size_t)b * 128 + bi) * 4;
    p[0] = zsum; p[1] = sdsum; p[2] = sdv; p[3] = sdlsd;
  }
}

// ---------------- fused: vertical coverage conv + reweight + 5x5 NMS (sm2 never stored) ----------------
// grid (9, 4, NB); block (32,8). Tile: output cols [60*bx, 60*bx+60), rows [128*by, +128).
// Each thread: one float2 col-pair (cols c0-2+2tx .. +1), 17 consecutive rows.
__global__ __launch_bounds__(256) void k_vcnms(const float* __restrict__ score,
                                               const float* __restrict__ wA) {
  __shared__ float red[256];
  __shared__ float2 xch[8][4][33];
  __shared__ int scnt, sbase;
  (void)wA;
  int b = blockIdx.z;
  int bx = blockIdx.x;
  int r0 = blockIdx.y * 128;
  int tx = threadIdx.x, ty = threadIdx.y;
  int tid = ty * 32 + tx;
  if (tid == 0) scnt = 0;
  float pv = (tid < 128) ? g_ps[b * 128 + tid] : 0.f;
  float Z = blkSum256(pv, red, tid);
  float invz = 1.0f / Z;
  int c2 = 30 * bx - 1 + tx;
  int c2c = min(max(c2, 0), 255);
  bool colok = (c2 >= 0 && c2 < 256);
  int rowbase = r0 - 2 + ty * 17;
  int hlo = rowbase - 25;
  const float2* pin = (const float2*)(g_t1c + (size_t)b * HWV);
  float2 s[17];
#pragma unroll
  for (int k = 0; k < 17; k++) s[k] = make_float2(0.f, 0.f);
  const float2* p = pin + (ptrdiff_t)hlo * 256 + c2c;
  if (hlo >= 0 && hlo + 66 < HH) vloop2<0, 67, 17, 50, 1, false>(p, hlo, s);
  else                           vloop2<0, 67, 17, 50, 1, true>(p, hlo, s);
  int w0 = 2 * c2, w1 = w0 + 1;
  int wc0 = min(max(w0, 0), 511), wc1 = min(max(w1, 0), 511);
  int jlo0 = max(25 - wc0, 0), jhi0 = min(536 - wc0, 50);
  int jlo1 = max(25 - wc1, 0), jhi1 = min(536 - wc1, 50);
  float Tw0 = g_WCP[jhi0 + 1] - g_WCP[jlo0];
  float Tw1 = g_WCP[jhi1 + 1] - g_WCP[jlo1];
  const float2* sc = (const float2*)(score + (size_t)b * HWV);
#pragma unroll
  for (int k = 0; k < 17; k++) {
    int g = rowbase + k;
    bool rowok = (g >= 0 && g < HH);
    float2 e = make_float2(0.f, 0.f);
    if (rowok) e = sc[(size_t)(rowok ? g : 0) * 256 + c2c];
    int gc = min(max(g, 0), 511);
    int ilo = max(25 - gc, 0), ihi = min(536 - gc, 50);
    float Tv = g_WCP[ihi + 1] - g_WCP[ilo];
    float ld0 = 1e4f * (invz * s[k].x + 1e-6f * Tw0 * Tv);
    float ld1 = 1e4f * (invz * s[k].y + 1e-6f * Tw1 * Tv);
    float v0 = __expf(e.x) * invz * rsqrtf(ld0 + 1e-8f);
    float v1 = __expf(e.y) * invz * rsqrtf(ld1 + 1e-8f);
    bool ok = rowok && colok;
    s[k].x = ok ? v0 : -INFINITY;
    s[k].y = ok ? v1 : -INFINITY;
  }
  // boundary-row exchange between ty neighbors
  xch[ty][0][tx] = s[0];  xch[ty][1][tx] = s[1];
  xch[ty][2][tx] = s[15]; xch[ty][3][tx] = s[16];
  __syncthreads();
  float2 ninf = make_float2(-INFINITY, -INFINITY);
  float2 bm2 = (ty > 0) ? xch[ty - 1][2][tx] : ninf;
  float2 bm1 = (ty > 0) ? xch[ty - 1][3][tx] : ninf;
  float2 ap0 = (ty < 7) ? xch[ty + 1][0][tx] : ninf;
  float2 ap1 = (ty < 7) ? xch[ty + 1][1][tx] : ninf;
  float mv[6]; int mi[6]; int mine = 0;
#pragma unroll
  for (int k = 0; k < 17; k++) {
    float2 a  = (k >= 2) ? s[k - 2] : (k == 1 ? bm1 : bm2);
    float2 bb = (k >= 1) ? s[k - 1] : bm1;
    float2 c  = s[k];
    float2 d  = (k < 16) ? s[k + 1] : ap0;
    float2 ee = (k < 15) ? s[k + 2] : (k == 15 ? ap0 : ap1);
    float2 vm;
    vm.x = fmaxf(fmaxf(fmaxf(a.x, bb.x), fmaxf(c.x, d.x)), ee.x);
    vm.y = fmaxf(fmaxf(fmaxf(a.y, bb.y), fmaxf(c.y, d.y)), ee.y);
    float Lx = __shfl_up_sync(0xffffffffu, vm.x, 1);
    float Ly = __shfl_up_sync(0xffffffffu, vm.y, 1);
    float Rx = __shfl_down_sync(0xffffffffu, vm.x, 1);
    float Ry = __shfl_down_sync(0xffffffffu, vm.y, 1);
    float Mx = fmaxf(fmaxf(Lx, Ly), fmaxf(fmaxf(vm.x, vm.y), Rx));
    float My = fmaxf(fmaxf(Ly, vm.x), fmaxf(fmaxf(vm.y, Rx), Ry));
    int g = rowbase + k;
    bool rowT = (g >= r0) && (g < r0 + 128) && (g < HH);
    if (rowT && tx >= 1 && tx <= 30) {
      if (w0 < WW && c.x == Mx) {
        if (mine < 6) { mv[mine] = c.x; mi[mine] = g * WW + w0; }
        mine++;
      }
      if (w1 < WW && c.y == My) {
        if (mine < 6) { mv[mine] = c.y; mi[mine] = g * WW + w1; }
        mine++;
      }
    }
  }
  int cnt = min(mine, 6);
  int loc = 0;
  if (cnt) loc = atomicAdd(&scnt, cnt);
  __syncthreads();
  if (tid == 0) sbase = atomicAdd(&g_svcnt[b], scnt);
  __syncthreads();
  int base = sbase + loc;
  for (int i = 0; i < cnt; i++) {
    int pp = base + i;
    if (pp < SCAP) {
      g_svval[(size_t)b * SCAP + pp] = mv[i];
      g_svidx[(size_t)b * SCAP + pp] = mi[i];
    }
  }
}

// ---------------- top-2048 radix select + gather + masked LSE ----------------
__global__ __launch_bounds__(1024) void k_topk(const float* __restrict__ scoremap,
                                               const float* __restrict__ vA,
                                               const float* __restrict__ vB) {
  int x = blockIdx.x;
  int n = g_svcnt[x]; if (n > SCAP) n = SCAP;
  const float* vals = g_svval + (size_t)x * SCAP;
  const int* idxs = g_svidx + (size_t)x * SCAP;
  int* out = g_kidx + (size_t)x * MM;
  __shared__ int hist[256];
  __shared__ int suf[256];
  __shared__ float red[1024];
  __shared__ int sh_k, sh_dig, sh_ngt, sh_neq;
  int t = threadIdx.x;
  unsigned int prefix = 0;
  int k = MM;
  for (int lvl = 0; lvl < 4; lvl++) {
    int shift = 24 - 8 * lvl;
    if (t < 256) hist[t] = 0;
    __syncthreads();
    for (int i = t; i < n; i += 1024) {
      unsigned int u = __float_as_uint(vals[i]);
      bool ok = (lvl == 0) || ((u >> (shift + 8)) == (prefix >> (shift + 8)));
      if (ok) atomicAdd(&hist[(u >> shift) & 255], 1);
    }
    __syncthreads();
    // parallel suffix scan over 256 digits
    if (t < 256) suf[t] = hist[t];
    __syncthreads();
    for (int off = 1; off < 256; off <<= 1) {
      int v = 0;
      if (t < 256) v = suf[t] + ((t + off < 256) ? suf[t + off] : 0);
      __syncthreads();
      if (t < 256) suf[t] = v;
      __syncthreads();
    }
    if (t < 256) {
      int nxt = (t == 255) ? 0 : suf[t + 1];
      if (suf[t] >= k && nxt < k) { sh_dig = t; sh_k = k - nxt; }
    }
    if (t == 0 && suf[0] < k) { sh_dig = 0; sh_k = k; }
    __syncthreads();
    k = sh_k;
    prefix |= ((unsigned int)sh_dig) << shift;
    __syncthreads();
  }
  unsigned int T = prefix;
  if (t == 0) { sh_ngt = 0; sh_neq = 0; }
  __syncthreads();
  for (int i = t; i < n; i += 1024) {
    unsigned int u = __float_as_uint(vals[i]);
    if (u > T) { int p = atomicAdd(&sh_ngt, 1); if (p < MM) out[p] = idxs[i]; }
  }
  __syncthreads();
  int base = sh_ngt;
  for (int i = t; i < n; i += 1024) {
    unsigned int u = __float_as_uint(vals[i]);
    if (u == T) { int p = atomicAdd(&sh_neq, 1); if (base + p < MM) out[base + p] = idxs[i]; }
  }
  __syncthreads();
  int dir = (x >= NB0) ? 1 : 0;
  int b = dir ? x - NB0 : x;
  const float* valid = (dir ? vB : vA) + (size_t)b * HWV;
  const float* logit = scoremap + (size_t)x * HWV;
  float mv = -INFINITY;
  for (int i = t; i < MM; i += 1024) {
    int id = out[i];
    float sl = logit[id];
    unsigned char lg = (valid[id] > 0.f) ? 1 : 0;
    g_ssl[(size_t)x * MM + i] = sl;
    g_slg[(size_t)x * MM + i] = lg;
    mv = fmaxf(mv, lg ? sl : -1e9f);
  }
  mv = blkMax1024(mv, red);
  float z = 0.f;
  for (int i = t; i < MM; i += 1024) {
    float ml = g_slg[(size_t)x * MM + i] ? g_ssl[(size_t)x * MM + i] : -1e9f;
    z += expf(ml - mv);
  }
  z = blkSum1024(z, red);
  if (t == 0) g_lse[x] = mv + logf(z);
}

// ---------------- distance + reward + weighted loss partials (2 queries/thread) ----------------
__global__ __launch_bounds__(128) void k_dist(const float* __restrict__ wA,
                                              const float* __restrict__ wB) {
  __shared__ float4 sp[MM];
  __shared__ float red[128];
  int x = blockIdx.x, seg = blockIdx.y;   // seg 0..7
  int dir = (x >= NB0) ? 1 : 0;
  int b = dir ? x - NB0 : x;
  int oppx = dir ? b : (NB0 + b);
  const int* opp = g_kidx + (size_t)oppx * MM;
  const int* own = g_kidx + (size_t)x * MM;
  const float4* warp = (const float4*)((dir ? wB : wA) + (size_t)b * HWV * 4);
  int t = threadIdx.x;
  for (int i = t; i < MM; i += 128) {
    int id = opp[i]; int hh = id >> 9, ww = id & 511;
    float px = ((float)ww + 0.5f) * (2.0f / (float)WW) - 1.0f;
    float py = ((float)hh + 0.5f) * (2.0f / (float)HH) - 1.0f;
    sp[i] = make_float4(2.0f * px, 2.0f * py, fmaf(px, px, py * py), 0.f);
  }
  __syncthreads();
  int i0 = seg * 128 + t;
  int i1 = i0 + 1024;
  float4 q0 = warp[own[i0]];
  float4 q1 = warp[own[i1]];
  float tx0 = q0.z, ty0 = q0.w;
  float tx1 = q1.z, ty1 = q1.w;
  float a0 = -3.4e38f, a1 = -3.4e38f, a2 = -3.4e38f, a3 = -3.4e38f;
  float b0 = -3.4e38f, b1 = -3.4e38f, b2 = -3.4e38f, b3 = -3.4e38f;
#pragma unroll 2
  for (int j = 0; j < MM; j += 4) {
    float4 p0 = sp[j], p1 = sp[j + 1], p2 = sp[j + 2], p3 = sp[j + 3];
    a0 = fmaxf(a0, fmaf(p0.x, tx0, fmaf(p0.y, ty0, -p0.z)));
    a1 = fmaxf(a1, fmaf(p1.x, tx0, fmaf(p1.y, ty0, -p1.z)));
    a2 = fmaxf(a2, fmaf(p2.x, tx0, fmaf(p2.y, ty0, -p2.z)));
    a3 = fmaxf(a3, fmaf(p3.x, tx0, fmaf(p3.y, ty0, -p3.z)));
    b0 = fmaxf(b0, fmaf(p0.x, tx1, fmaf(p0.y, ty1, -p0.z)));
    b1 = fmaxf(b1, fmaf(p1.x, tx1, fmaf(p1.y, ty1, -p1.z)));
    b2 = fmaxf(b2, fmaf(p2.x, tx1, fmaf(p2.y, ty1, -p2.z)));
    b3 = fmaxf(b3, fmaf(p3.x, tx1, fmaf(p3.y, ty1, -p3.z)));
  }
  float m0 = fmaxf(fmaxf(a0, a1), fmaxf(a2, a3));
  float m1 = fmaxf(fmaxf(b0, b1), fmaxf(b2, b3));
  float dm0 = fmaxf(fmaf(tx0, tx0, ty0 * ty0) - m0, 0.f);
  float dm1 = fmaxf(fmaf(tx1, tx1, ty1 * ty1) - m1, 0.f);
  float r0 = expf(-100.0f * sqrtf(dm0 + 1e-12f));
  float r1 = expf(-100.0f * sqrtf(dm1 + 1e-12f));
  float lse = g_lse[x];
  float c0 = g_slg[(size_t)x * MM + i0] ? r0 * (g_ssl[(size_t)x * MM + i0] - lse) : 0.f;
  float c1 = g_slg[(size_t)x * MM + i1] ? r1 * (g_ssl[(size_t)x * MM + i1] - lse) : 0.f;
  float contrib = blkSum128(c0 + c1, red, t);
  if (t == 0) g_spart[x * 8 + seg] = contrib;
}

// ---------------- final combine ----------------
__global__ __launch_bounds__(256) void k_final(float* __restrict__ out) {
  __shared__ float sZ[128], sS[128], sV[128], sD[128];
  __shared__ float sm[16];
  __shared__ float ssp[128];
  int t = threadIdx.x;
  if (t < 128) {
    int img = t >> 3, seg = t & 7;
    float z = 0.f, s = 0.f, v = 0.f, d = 0.f;
    for (int j = 0; j < 16; j++) {
      const float* p = g_mpart + ((size_t)img * 128 + seg * 16 + j) * 4;
      z += p[0]; s += p[1]; v += p[2]; d += p[3];
    }
    sZ[t] = z; sS[t] = s; sV[t] = v; sD[t] = d;
    ssp[t] = g_spart[t];
  }
  __syncthreads();
  if (t < 16) {
    float z = 0.f, s = 0.f, v = 0.f, d = 0.f;
    for (int seg = 0; seg < 8; seg++) {
      z += sZ[t * 8 + seg]; s += sS[t * 8 + seg];
      v += sV[t * 8 + seg]; d += sD[t * 8 + seg];
    }
    float inv = 1.0f / s;
    sm[t] = inv * (d - v) - logf(s) + logf(z);
  }
  __syncthreads();
  if (t == 0) {
    float sp = 0.f;
    for (int i = 0; i < 128; i++) sp += ssp[i];
    float m = 0.f;
    for (int i = 0; i < 16; i++) m += sm[i];
    out[0] = -sp + m * (1.0f / 16.0f);
  }
}

// ---------------- host launcher ----------------
extern "C" void kernel_launch(void* const* d_in, const int* in_sizes, int n_in,
                              void* d_out, int out_size) {
  (void)in_sizes; (void)n_in; (void)out_size;
  const float* scoremap = (const float*)d_in[0];
  const float* wA = (const float*)d_in[1];
  const float* wB = (const float*)d_in[2];
  const float* vA = (const float*)d_in[3];
  const float* vB = (const float*)d_in[4];
  const float* hd = (const float*)d_in[5];
  float* out = (float*)d_out;

  dim3 hg(HH / 4, NB);
  dim3 hb(64, 4);
  dim3 vg(WW / 64, HH / 64, NB);
  dim3 vb(32, 8);
  dim3 cg(9, 4, NB);
  dim3 dg(NB, 8);

  k_hall<<<hg, hb>>>(scoremap, hd);
  k_vmatch<<<vg, vb>>>();
  k_vcnms<<<cg, vb>>>(scoremap, wA);
  k_topk<<<NB, 1024>>>(scoremap, vA, vB);
  k_dist<<<dg, 128>>>(wA, wB);
  k_final<<<1, 256>>>(out);
}